// round 9
// baseline (speedup 1.0000x reference)
#include <cuda_runtime.h>
#include <math.h>

// ---------------------------------------------------------------------------
// Problem constants: B=4, N=16384 (H=W=128), C=128, HEADS=2, dh=64, SR=4
// ---------------------------------------------------------------------------
#define BATCH   4
#define NQ      16384
#define C_DIM   128
#define HEADS   2
#define DH      64
#define NKV     1024
#define QTILE   128
#define KCH     32
#define KCONV   2048

// Scratch (allocation-free rule: __device__ globals)
__device__ float g_q  [BATCH * NQ  * C_DIM];
__device__ float g_xr [BATCH * NKV * C_DIM];
__device__ float g_k  [BATCH * NKV * C_DIM];
__device__ float g_v  [BATCH * NKV * C_DIM];
__device__ float g_ao [BATCH * NQ  * C_DIM];
__device__ float g_wtq[C_DIM * C_DIM];     // transposed tf32 weights [n][k]
__device__ float g_wtk[C_DIM * C_DIM];
__device__ float g_wtv[C_DIM * C_DIM];
__device__ float g_wtp[C_DIM * C_DIM];
__device__ float g_wct[C_DIM * KCONV];     // conv weight transposed [n][k]

// ---------------------------------------------------------------------------
// tf32 helpers (fragment mappings validated in R5/R6)
// ---------------------------------------------------------------------------
__device__ __forceinline__ unsigned f2tf(float x) {
    unsigned r;
    asm("cvt.rna.tf32.f32 %0, %1;" : "=r"(r) : "f"(x));
    return r;
}
__device__ __forceinline__ float f2tff(float x) {
    return __uint_as_float(f2tf(x));
}
__device__ __forceinline__ void mma_tf32(float& d0, float& d1, float& d2, float& d3,
                                         unsigned a0, unsigned a1, unsigned a2, unsigned a3,
                                         unsigned b0, unsigned b1) {
    asm volatile(
        "mma.sync.aligned.m16n8k8.row.col.f32.tf32.tf32.f32 "
        "{%0,%1,%2,%3},{%4,%5,%6,%7},{%8,%9},{%0,%1,%2,%3};"
        : "+f"(d0), "+f"(d1), "+f"(d2), "+f"(d3)
        : "r"(a0), "r"(a1), "r"(a2), "r"(a3), "r"(b0), "r"(b1));
}

// Permuted scatter-store into kg-blocked smem: chunk layout [kg][row][16],
// pos(k) = (k&3)*4 + (k>>2) within the 16-k group. A float4 of consecutive k
// (c4*4..+3) lands at stride-4 positions with column offset (c4&3).
__device__ __forceinline__ void sts_perm(float* s, int rows16, int row, int c4, float4 v) {
    float* base = s + ((c4 >> 2) * rows16 * 16) + row * 16 + (c4 & 3);
    base[0] = v.x; base[4] = v.y; base[8] = v.z; base[12] = v.w;
}

// ---------------------------------------------------------------------------
// Weight prep: batched transpose of four [128][128] mats -> [n][k], tf32.
// grid (4,4,4): z selects matrix. block (32,8).
// ---------------------------------------------------------------------------
__global__ void transpose4_tf32_kernel(const float* __restrict__ s0, const float* __restrict__ s1,
                                       const float* __restrict__ s2, const float* __restrict__ s3,
                                       float* __restrict__ d0, float* __restrict__ d1,
                                       float* __restrict__ d2, float* __restrict__ d3) {
    const float* src = (blockIdx.z == 0) ? s0 : (blockIdx.z == 1) ? s1 : (blockIdx.z == 2) ? s2 : s3;
    float*       dst = (blockIdx.z == 0) ? d0 : (blockIdx.z == 1) ? d1 : (blockIdx.z == 2) ? d2 : d3;
    __shared__ float tile[32][33];
    int kb = blockIdx.x << 5, nb = blockIdx.y << 5;
    int tx = threadIdx.x, ty = threadIdx.y;
#pragma unroll
    for (int r = 0; r < 32; r += 8)
        tile[ty + r][tx] = src[(size_t)(kb + ty + r) * 128 + nb + tx];
    __syncthreads();
#pragma unroll
    for (int r = 0; r < 32; r += 8)
        dst[(size_t)(nb + ty + r) * 128 + kb + tx] = f2tff(tile[tx][ty + r]);
}

__global__ void transpose_tf32_kernel(const float* __restrict__ src,
                                      float* __restrict__ dst, int K) {
    __shared__ float tile[32][33];
    int kb = blockIdx.x << 5, nb = blockIdx.y << 5;
    int tx = threadIdx.x, ty = threadIdx.y;
#pragma unroll
    for (int r = 0; r < 32; r += 8)
        tile[ty + r][tx] = src[(size_t)(kb + ty + r) * 128 + nb + tx];
    __syncthreads();
#pragma unroll
    for (int r = 0; r < 32; r += 8)
        dst[(size_t)(nb + ty + r) * K + kb + tx] = f2tff(tile[tx][ty + r]);
}

// ---------------------------------------------------------------------------
// tf32 tensor-core GEMM v2: out[M,128] = A[M,128] @ W (Wt pre-transposed).
// BM=128, 8 warps x 16 rows x full 128 cols. Register-prefetch double buffer,
// k-interleaved smem -> all fragment reads are conflict-free LDS.128.
// ---------------------------------------------------------------------------
__global__ __launch_bounds__(256)
void gemm_tf32_kernel(const float* __restrict__ A, const float* __restrict__ Wt,
                      float* __restrict__ out) {
    __shared__ float sA[2 * 128 * 16];   // [kg][row][pos16]
    __shared__ float sW[2 * 128 * 16];
    int m0 = blockIdx.x << 7;
    int tid = threadIdx.x;
    int w = tid >> 5, lane = tid & 31;
    int gid = lane >> 2, tig = lane & 3;

    float oacc[16][4];
#pragma unroll
    for (int i = 0; i < 16; i++)
#pragma unroll
        for (int j = 0; j < 4; j++) oacc[i][j] = 0.f;

    float4 av[4], wv[4];
    // prologue: load chunk 0
#pragma unroll
    for (int i = 0; i < 4; i++) {
        int f = tid + (i << 8);
        int row = f >> 3, c4 = f & 7;
        av[i] = *(const float4*)&A [(size_t)(m0 + row) * 128 + (c4 << 2)];
        wv[i] = *(const float4*)&Wt[(size_t)row * 128 + (c4 << 2)];
    }
#pragma unroll
    for (int i = 0; i < 4; i++) {
        int f = tid + (i << 8);
        int row = f >> 3, c4 = f & 7;
        float4 a = av[i];
        a.x = f2tff(a.x); a.y = f2tff(a.y); a.z = f2tff(a.z); a.w = f2tff(a.w);
        sts_perm(sA, 128, row, c4, a);
        sts_perm(sW, 128, row, c4, wv[i]);
    }
    __syncthreads();

#pragma unroll
    for (int kc = 0; kc < 4; kc++) {
        if (kc < 3) {   // prefetch next chunk (overlaps MMA below)
            int k0 = (kc + 1) << 5;
#pragma unroll
            for (int i = 0; i < 4; i++) {
                int f = tid + (i << 8);
                int row = f >> 3, c4 = f & 7;
                av[i] = *(const float4*)&A [(size_t)(m0 + row) * 128 + k0 + (c4 << 2)];
                wv[i] = *(const float4*)&Wt[(size_t)row * 128 + k0 + (c4 << 2)];
            }
        }
#pragma unroll
        for (int kg = 0; kg < 2; kg++) {
            const float* pa = &sA[kg * 2048 + (w * 16 + gid) * 16 + (tig << 2)];
            float4 alo = *(const float4*)pa;
            float4 ahi = *(const float4*)(pa + 8 * 16);
            unsigned a0 = __float_as_uint(alo.x), a1 = __float_as_uint(ahi.x);
            unsigned a2 = __float_as_uint(alo.y), a3 = __float_as_uint(ahi.y);
            unsigned c0 = __float_as_uint(alo.z), c1 = __float_as_uint(ahi.z);
            unsigned c2 = __float_as_uint(alo.w), c3 = __float_as_uint(ahi.w);
#pragma unroll
            for (int nt = 0; nt < 16; nt++) {
                float4 bv = *(const float4*)&sW[kg * 2048 + (nt * 8 + gid) * 16 + (tig << 2)];
                mma_tf32(oacc[nt][0], oacc[nt][1], oacc[nt][2], oacc[nt][3],
                         a0, a1, a2, a3, __float_as_uint(bv.x), __float_as_uint(bv.y));
                mma_tf32(oacc[nt][0], oacc[nt][1], oacc[nt][2], oacc[nt][3],
                         c0, c1, c2, c3, __float_as_uint(bv.z), __float_as_uint(bv.w));
            }
        }
        if (kc < 3) {
            __syncthreads();
#pragma unroll
            for (int i = 0; i < 4; i++) {
                int f = tid + (i << 8);
                int row = f >> 3, c4 = f & 7;
                float4 a = av[i];
                a.x = f2tff(a.x); a.y = f2tff(a.y); a.z = f2tff(a.z); a.w = f2tff(a.w);
                sts_perm(sA, 128, row, c4, a);
                sts_perm(sW, 128, row, c4, wv[i]);
            }
            __syncthreads();
        }
    }

    size_t r0 = (size_t)(m0 + w * 16 + gid) * 128;
    size_t r1 = r0 + 8 * 128;
#pragma unroll
    for (int nt = 0; nt < 16; nt++) {
        int c = nt * 8 + 2 * tig;
        *(float2*)&out[r0 + c] = make_float2(oacc[nt][0], oacc[nt][1]);
        *(float2*)&out[r1 + c] = make_float2(oacc[nt][2], oacc[nt][3]);
    }
}

// ---------------------------------------------------------------------------
// tf32 conv (4x4 stride-4 patch GEMM, K=2048) + bias + LayerNorm, v2.
// BM=32 -> 128 blocks. rg=w&1 (16-row group), cg=w>>1 (32-col group).
// Register-prefetch + k-interleaved smem (LDS.128 fragment reads).
// ---------------------------------------------------------------------------
__global__ __launch_bounds__(256)
void conv_ln_tf32_kernel(const float* __restrict__ x, const float* __restrict__ Wct,
                         const float* __restrict__ bias, const float* __restrict__ gamma,
                         const float* __restrict__ beta, float* __restrict__ out) {
    __shared__ float sA[2 * 32 * 16];    // [kg][row][pos16]
    __shared__ float sW[2 * 128 * 16];
    __shared__ float sred[32 * 4], sredq[32 * 4];
    __shared__ float sMu[32], sRs[32];

    int m0 = blockIdx.x << 5;
    int tid = threadIdx.x;
    int w = tid >> 5, lane = tid & 31;
    int gid = lane >> 2, tig = lane & 3;
    int rg = w & 1, cg = w >> 1;

    // fixed loader coords: A: 1 float4/thread; W: 4 float4/thread
    int arow = tid >> 3, ac4 = tid & 7;
    // A source pixel for this block row (b, oh, ow fixed per row)
    int am = m0 + arow;
    int ab = am >> 10, apos = am & 1023, aoh = apos >> 5, aow = apos & 31;
    const float* abase = x + ((size_t)((ab * 128 + (aoh << 2)) * 128 + (aow << 2))) * 128;

    float oacc[4][4];
#pragma unroll
    for (int i = 0; i < 4; i++)
#pragma unroll
        for (int j = 0; j < 4; j++) oacc[i][j] = 0.f;

    float4 av, wv[4];
    {   // prologue: chunk 0 (kh=0, kw=0, ci0=0)
        av = *(const float4*)(abase + (ac4 << 2));
#pragma unroll
        for (int i = 0; i < 4; i++) {
            int f = tid + (i << 8);
            int n = f >> 3, c4 = f & 7;
            wv[i] = *(const float4*)&Wct[(size_t)n * KCONV + (c4 << 2)];
        }
        float4 a = av;
        a.x = f2tff(a.x); a.y = f2tff(a.y); a.z = f2tff(a.z); a.w = f2tff(a.w);
        sts_perm(sA, 32, arow, ac4, a);
#pragma unroll
        for (int i = 0; i < 4; i++) {
            int f = tid + (i << 8);
            int n = f >> 3, c4 = f & 7;
            sts_perm(sW, 128, n, c4, wv[i]);
        }
    }
    __syncthreads();

#pragma unroll 1
    for (int kc = 0; kc < 64; kc++) {
        if (kc < 63) {   // prefetch next chunk
            int k0 = (kc + 1) << 5;
            int kh = k0 >> 9, kw = (k0 >> 7) & 3, ci0 = k0 & 127;
            av = *(const float4*)(abase + ((size_t)(kh * 128 + kw)) * 128 + ci0 + (ac4 << 2));
#pragma unroll
            for (int i = 0; i < 4; i++) {
                int f = tid + (i << 8);
                int n = f >> 3, c4 = f & 7;
                wv[i] = *(const float4*)&Wct[(size_t)n * KCONV + k0 + (c4 << 2)];
            }
        }
#pragma unroll
        for (int kg = 0; kg < 2; kg++) {
            const float* pa = &sA[kg * 512 + (rg * 16 + gid) * 16 + (tig << 2)];
            float4 alo = *(const float4*)pa;
            float4 ahi = *(const float4*)(pa + 8 * 16);
            unsigned a0 = __float_as_uint(alo.x), a1 = __float_as_uint(ahi.x);
            unsigned a2 = __float_as_uint(alo.y), a3 = __float_as_uint(ahi.y);
            unsigned c0 = __float_as_uint(alo.z), c1 = __float_as_uint(ahi.z);
            unsigned c2 = __float_as_uint(alo.w), c3 = __float_as_uint(ahi.w);
#pragma unroll
            for (int nt = 0; nt < 4; nt++) {
                float4 bv = *(const float4*)&sW[kg * 2048 + (cg * 32 + nt * 8 + gid) * 16 + (tig << 2)];
                mma_tf32(oacc[nt][0], oacc[nt][1], oacc[nt][2], oacc[nt][3],
                         a0, a1, a2, a3, __float_as_uint(bv.x), __float_as_uint(bv.y));
                mma_tf32(oacc[nt][0], oacc[nt][1], oacc[nt][2], oacc[nt][3],
                         c0, c1, c2, c3, __float_as_uint(bv.z), __float_as_uint(bv.w));
            }
        }
        if (kc < 63) {
            __syncthreads();
            {
                float4 a = av;
                a.x = f2tff(a.x); a.y = f2tff(a.y); a.z = f2tff(a.z); a.w = f2tff(a.w);
                sts_perm(sA, 32, arow, ac4, a);
#pragma unroll
                for (int i = 0; i < 4; i++) {
                    int f = tid + (i << 8);
                    int n = f >> 3, c4 = f & 7;
                    sts_perm(sW, 128, n, c4, wv[i]);
                }
            }
            __syncthreads();
        }
    }

    // ---- epilogue: +bias, LayerNorm over C=128 ----
    float s0 = 0.f, s0q = 0.f, s1 = 0.f, s1q = 0.f;
#pragma unroll
    for (int nt = 0; nt < 4; nt++) {
        int c = cg * 32 + nt * 8 + 2 * tig;
        float b0v = bias[c], b1v = bias[c + 1];
        oacc[nt][0] += b0v; oacc[nt][1] += b1v;
        oacc[nt][2] += b0v; oacc[nt][3] += b1v;
        s0  += oacc[nt][0] + oacc[nt][1];
        s0q += oacc[nt][0] * oacc[nt][0] + oacc[nt][1] * oacc[nt][1];
        s1  += oacc[nt][2] + oacc[nt][3];
        s1q += oacc[nt][2] * oacc[nt][2] + oacc[nt][3] * oacc[nt][3];
    }
    s0  += __shfl_xor_sync(0xffffffffu, s0, 1);  s0  += __shfl_xor_sync(0xffffffffu, s0, 2);
    s0q += __shfl_xor_sync(0xffffffffu, s0q, 1); s0q += __shfl_xor_sync(0xffffffffu, s0q, 2);
    s1  += __shfl_xor_sync(0xffffffffu, s1, 1);  s1  += __shfl_xor_sync(0xffffffffu, s1, 2);
    s1q += __shfl_xor_sync(0xffffffffu, s1q, 1); s1q += __shfl_xor_sync(0xffffffffu, s1q, 2);
    if (tig == 0) {
        int r0 = rg * 16 + gid;
        sred [r0 * 4 + cg] = s0;  sredq[r0 * 4 + cg] = s0q;
        sred [(r0 + 8) * 4 + cg] = s1;  sredq[(r0 + 8) * 4 + cg] = s1q;
    }
    __syncthreads();
    if (tid < 32) {
        float s = 0.f, sq = 0.f;
#pragma unroll
        for (int t = 0; t < 4; t++) { s += sred[tid * 4 + t]; sq += sredq[tid * 4 + t]; }
        float mu  = s * 0.0078125f;
        float var = sq * 0.0078125f - mu * mu;
        sMu[tid] = mu;
        sRs[tid] = rsqrtf(var + 1e-6f);
    }
    __syncthreads();
    int r0 = rg * 16 + gid, r1 = r0 + 8;
    float mu0 = sMu[r0], rs0 = sRs[r0], mu1 = sMu[r1], rs1 = sRs[r1];
#pragma unroll
    for (int nt = 0; nt < 4; nt++) {
        int c = cg * 32 + nt * 8 + 2 * tig;
        float g0 = gamma[c], g1 = gamma[c + 1], be0 = beta[c], be1 = beta[c + 1];
        *(float2*)&out[(size_t)(m0 + r0) * 128 + c] =
            make_float2((oacc[nt][0] - mu0) * rs0 * g0 + be0,
                        (oacc[nt][1] - mu0) * rs0 * g1 + be1);
        *(float2*)&out[(size_t)(m0 + r1) * 128 + c] =
            make_float2((oacc[nt][2] - mu1) * rs1 * g0 + be0,
                        (oacc[nt][3] - mu1) * rs1 * g1 + be1);
    }
}

// ---------------------------------------------------------------------------
// tf32 tensor-core flash attention (unchanged — validated R5/R6)
// ---------------------------------------------------------------------------
__global__ __launch_bounds__(256)
void attn_mma_kernel(const float* __restrict__ Q, const float* __restrict__ K,
                     const float* __restrict__ V, float* __restrict__ O) {
    __shared__ float sK[KCH * 68];
    __shared__ float sV[KCH * 72];
    __shared__ float sP[QTILE * 36];

    int b  = blockIdx.z, h = blockIdx.y;
    int n0 = blockIdx.x * QTILE;
    int tid  = threadIdx.x;
    int w    = tid >> 5;
    int lane = tid & 31;
    int gid  = lane >> 2;
    int tig  = lane & 3;

    unsigned qa[8][4];
    {
        const float* qb = Q + ((size_t)(b * NQ + n0 + w * 16)) * C_DIM + h * DH;
#pragma unroll
        for (int ks = 0; ks < 8; ks++) {
            int c = ks * 8 + tig;
            qa[ks][0] = f2tf(qb[(size_t)gid       * C_DIM + c    ] * 0.125f);
            qa[ks][1] = f2tf(qb[(size_t)(gid + 8) * C_DIM + c    ] * 0.125f);
            qa[ks][2] = f2tf(qb[(size_t)gid       * C_DIM + c + 4] * 0.125f);
            qa[ks][3] = f2tf(qb[(size_t)(gid + 8) * C_DIM + c + 4] * 0.125f);
        }
    }

    const float* kb_ = K + (size_t)(b * NKV) * C_DIM + h * DH;
    const float* vb_ = V + (size_t)(b * NKV) * C_DIM + h * DH;

    float oacc[8][4];
#pragma unroll
    for (int i = 0; i < 8; i++)
#pragma unroll
        for (int j = 0; j < 4; j++) oacc[i][j] = 0.f;
    float m0r = -1e30f, m1r = -1e30f, l0 = 0.f, l1 = 0.f;

#pragma unroll 1
    for (int kc = 0; kc < NKV / KCH; kc++) {
        __syncthreads();
#pragma unroll
        for (int i = 0; i < 2; i++) {
            int f = tid + (i << 8);
            int row = f >> 4, c4 = f & 15;
            size_t go = (size_t)(kc * KCH + row) * C_DIM + (c4 << 2);
            float4 kv = *(const float4*)(kb_ + go);
            float4 vv = *(const float4*)(vb_ + go);
            float4 kt, vt;
            kt.x = f2tff(kv.x); kt.y = f2tff(kv.y); kt.z = f2tff(kv.z); kt.w = f2tff(kv.w);
            vt.x = f2tff(vv.x); vt.y = f2tff(vv.y); vt.z = f2tff(vv.z); vt.w = f2tff(vv.w);
            *(float4*)&sK[row * 68 + (c4 << 2)] = kt;
            *(float4*)&sV[row * 72 + (c4 << 2)] = vt;
        }
        __syncthreads();

        float sacc[4][4];
#pragma unroll
        for (int i = 0; i < 4; i++)
#pragma unroll
            for (int j = 0; j < 4; j++) sacc[i][j] = 0.f;
#pragma unroll
        for (int ks = 0; ks < 8; ks++) {
#pragma unroll
            for (int nt = 0; nt < 4; nt++) {
                unsigned b0 = __float_as_uint(sK[(nt * 8 + gid) * 68 + ks * 8 + tig]);
                unsigned b1 = __float_as_uint(sK[(nt * 8 + gid) * 68 + ks * 8 + tig + 4]);
                mma_tf32(sacc[nt][0], sacc[nt][1], sacc[nt][2], sacc[nt][3],
                         qa[ks][0], qa[ks][1], qa[ks][2], qa[ks][3], b0, b1);
            }
        }

        float cm0 = -1e30f, cm1 = -1e30f;
#pragma unroll
        for (int nt = 0; nt < 4; nt++) {
            cm0 = fmaxf(cm0, fmaxf(sacc[nt][0], sacc[nt][1]));
            cm1 = fmaxf(cm1, fmaxf(sacc[nt][2], sacc[nt][3]));
        }
        cm0 = fmaxf(cm0, __shfl_xor_sync(0xffffffffu, cm0, 1));
        cm0 = fmaxf(cm0, __shfl_xor_sync(0xffffffffu, cm0, 2));
        cm1 = fmaxf(cm1, __shfl_xor_sync(0xffffffffu, cm1, 1));
        cm1 = fmaxf(cm1, __shfl_xor_sync(0xffffffffu, cm1, 2));
        float mn0 = fmaxf(m0r, cm0), mn1 = fmaxf(m1r, cm1);
        float al0 = __expf(m0r - mn0), al1 = __expf(m1r - mn1);
        float ps0 = 0.f, ps1 = 0.f;
        int r0off = (w * 16 + gid) * 36;
        int r1off = (w * 16 + gid + 8) * 36;
#pragma unroll
        for (int nt = 0; nt < 4; nt++) {
            float p0 = __expf(sacc[nt][0] - mn0);
            float p1 = __expf(sacc[nt][1] - mn0);
            float p2 = __expf(sacc[nt][2] - mn1);
            float p3 = __expf(sacc[nt][3] - mn1);
            ps0 += p0 + p1;
            ps1 += p2 + p3;
            int co = nt * 8 + 2 * tig;
            float2 e0, e1;
            e0.x = f2tff(p0); e0.y = f2tff(p1);
            e1.x = f2tff(p2); e1.y = f2tff(p3);
            *(float2*)&sP[r0off + co] = e0;
            *(float2*)&sP[r1off + co] = e1;
        }
        ps0 += __shfl_xor_sync(0xffffffffu, ps0, 1);
        ps0 += __shfl_xor_sync(0xffffffffu, ps0, 2);
        ps1 += __shfl_xor_sync(0xffffffffu, ps1, 1);
        ps1 += __shfl_xor_sync(0xffffffffu, ps1, 2);
        l0 = l0 * al0 + ps0;  m0r = mn0;
        l1 = l1 * al1 + ps1;  m1r = mn1;
#pragma unroll
        for (int nt = 0; nt < 8; nt++) {
            oacc[nt][0] *= al0; oacc[nt][1] *= al0;
            oacc[nt][2] *= al1; oacc[nt][3] *= al1;
        }
        __syncwarp();

#pragma unroll
        for (int ks = 0; ks < 4; ks++) {
            unsigned a0 = __float_as_uint(sP[r0off + ks * 8 + tig]);
            unsigned a1 = __float_as_uint(sP[r1off + ks * 8 + tig]);
            unsigned a2 = __float_as_uint(sP[r0off + ks * 8 + tig + 4]);
            unsigned a3 = __float_as_uint(sP[r1off + ks * 8 + tig + 4]);
#pragma unroll
            for (int nt = 0; nt < 8; nt++) {
                unsigned b0 = __float_as_uint(sV[(ks * 8 + tig)     * 72 + nt * 8 + gid]);
                unsigned b1 = __float_as_uint(sV[(ks * 8 + tig + 4) * 72 + nt * 8 + gid]);
                mma_tf32(oacc[nt][0], oacc[nt][1], oacc[nt][2], oacc[nt][3],
                         a0, a1, a2, a3, b0, b1);
            }
        }
    }

    float inv0 = 1.f / l0, inv1 = 1.f / l1;
    float* ob = O + ((size_t)(b * NQ + n0 + w * 16)) * C_DIM + h * DH;
#pragma unroll
    for (int nt = 0; nt < 8; nt++) {
        int d = nt * 8 + 2 * tig;
        float2 r0v, r1v;
        r0v.x = oacc[nt][0] * inv0; r0v.y = oacc[nt][1] * inv0;
        r1v.x = oacc[nt][2] * inv1; r1v.y = oacc[nt][3] * inv1;
        *(float2*)(ob + (size_t)gid       * C_DIM + d) = r0v;
        *(float2*)(ob + (size_t)(gid + 8) * C_DIM + d) = r1v;
    }
}

// ---------------------------------------------------------------------------
// Launch. Inputs: x, Wq, Wk, Wv, Wproj, sr_kernel, sr_bias, gamma, beta.
// ---------------------------------------------------------------------------
extern "C" void kernel_launch(void* const* d_in, const int* in_sizes, int n_in,
                              void* d_out, int out_size) {
    const float* x     = (const float*)d_in[0];
    const float* Wq    = (const float*)d_in[1];
    const float* Wk    = (const float*)d_in[2];
    const float* Wv    = (const float*)d_in[3];
    const float* Wp    = (const float*)d_in[4];
    const float* Wsr   = (const float*)d_in[5];
    const float* bias  = (const float*)d_in[6];
    const float* gamma = (const float*)d_in[7];
    const float* beta  = (const float*)d_in[8];

    float *q, *xr, *k, *v, *ao, *wtq, *wtk, *wtv, *wtp, *wct;
    cudaGetSymbolAddress((void**)&q,   g_q);
    cudaGetSymbolAddress((void**)&xr,  g_xr);
    cudaGetSymbolAddress((void**)&k,   g_k);
    cudaGetSymbolAddress((void**)&v,   g_v);
    cudaGetSymbolAddress((void**)&ao,  g_ao);
    cudaGetSymbolAddress((void**)&wtq, g_wtq);
    cudaGetSymbolAddress((void**)&wtk, g_wtk);
    cudaGetSymbolAddress((void**)&wtv, g_wtv);
    cudaGetSymbolAddress((void**)&wtp, g_wtp);
    cudaGetSymbolAddress((void**)&wct, g_wct);

    dim3 tb(32, 8);
    transpose4_tf32_kernel<<<dim3(4, 4, 4), tb>>>(Wq, Wk, Wv, Wp, wtq, wtk, wtv, wtp);
    transpose_tf32_kernel<<<dim3(64, 4), tb>>>(Wsr, wct, KCONV);

    gemm_tf32_kernel<<<(BATCH * NQ) / 128, 256>>>(x, wtq, q);                   // Q proj
    conv_ln_tf32_kernel<<<(BATCH * NKV) / 32, 256>>>(x, wct, bias, gamma, beta, xr);
    gemm_tf32_kernel<<<(BATCH * NKV) / 128, 256>>>(xr, wtk, k);                 // K proj
    gemm_tf32_kernel<<<(BATCH * NKV) / 128, 256>>>(xr, wtv, v);                 // V proj
    attn_mma_kernel<<<dim3(NQ / QTILE, HEADS, BATCH), 256>>>(q, k, v, ao);      // attention
    gemm_tf32_kernel<<<(BATCH * NQ) / 128, 256>>>(ao, wtp, (float*)d_out);      // out proj
}

// round 10
// speedup vs baseline: 1.1932x; 1.1932x over previous
#include <cuda_runtime.h>
#include <math.h>

// ---------------------------------------------------------------------------
// Problem constants: B=4, N=16384 (H=W=128), C=128, HEADS=2, dh=64, SR=4
// ---------------------------------------------------------------------------
#define BATCH   4
#define NQ      16384
#define C_DIM   128
#define HEADS   2
#define DH      64
#define NKV     1024
#define QTILE   128
#define KCH     32
#define KCONV   2048
#define MCONV   (BATCH * NKV)     // 4096

// Scratch (allocation-free rule: __device__ globals)
__device__ float g_q    [BATCH * NQ  * C_DIM];
__device__ float g_xr   [BATCH * NKV * C_DIM];
__device__ float g_k    [BATCH * NKV * C_DIM];
__device__ float g_v    [BATCH * NKV * C_DIM];
__device__ float g_ao   [BATCH * NQ  * C_DIM];
__device__ float g_cpart[4 * MCONV * C_DIM];      // conv split-K partials
// Pre-permuted tf32 weights, fragment-ready layout:
//   [kcg][n][pos16],  kcg = kc*2+kg,  k = kc*32 + kg*16 + ((pos>>2) + (pos&3)*4)
__device__ float g_wtq[C_DIM * C_DIM];
__device__ float g_wtk[C_DIM * C_DIM];
__device__ float g_wtv[C_DIM * C_DIM];
__device__ float g_wtp[C_DIM * C_DIM];
__device__ float g_wct[C_DIM * KCONV];

// ---------------------------------------------------------------------------
// tf32 helpers (fragment mappings validated R5-R9)
// ---------------------------------------------------------------------------
__device__ __forceinline__ unsigned f2tf(float x) {
    unsigned r;
    asm("cvt.rna.tf32.f32 %0, %1;" : "=r"(r) : "f"(x));
    return r;
}
__device__ __forceinline__ float f2tff(float x) {
    return __uint_as_float(f2tf(x));
}
__device__ __forceinline__ void mma_tf32(float& d0, float& d1, float& d2, float& d3,
                                         unsigned a0, unsigned a1, unsigned a2, unsigned a3,
                                         unsigned b0, unsigned b1) {
    asm volatile(
        "mma.sync.aligned.m16n8k8.row.col.f32.tf32.tf32.f32 "
        "{%0,%1,%2,%3},{%4,%5,%6,%7},{%8,%9},{%0,%1,%2,%3};"
        : "+f"(d0), "+f"(d1), "+f"(d2), "+f"(d3)
        : "r"(a0), "r"(a1), "r"(a2), "r"(a3), "r"(b0), "r"(b1));
}

// Permuted scatter-store for activations: chunk layout [kg][row][pos16],
// pos(k) = (k&3)*4 + (k>>2) within a 16-k group (4x4 transpose, involution).
__device__ __forceinline__ void sts_perm(float* s, int rows16, int row, int c4, float4 v) {
    float* base = s + ((c4 >> 2) * rows16 * 16) + row * 16 + (c4 & 3);
    base[0] = v.x; base[4] = v.y; base[8] = v.z; base[12] = v.w;
}

// ---------------------------------------------------------------------------
// Weight pack kernels: src [K][128] -> permuted fragment layout, tf32.
// ---------------------------------------------------------------------------
__global__ void pack_w4_kernel(const float* __restrict__ s0, const float* __restrict__ s1,
                               const float* __restrict__ s2, const float* __restrict__ s3,
                               float* __restrict__ d0, float* __restrict__ d1,
                               float* __restrict__ d2, float* __restrict__ d3) {
    int id = blockIdx.x * 256 + threadIdx.x;            // 0..65535
    int mat = id >> 14, e = id & 16383;
    const float* s = (mat == 0) ? s0 : (mat == 1) ? s1 : (mat == 2) ? s2 : s3;
    float*       d = (mat == 0) ? d0 : (mat == 1) ? d1 : (mat == 2) ? d2 : d3;
    int pos = e & 15, n = (e >> 4) & 127, kcg = e >> 11;
    int k = (kcg >> 1) * 32 + (kcg & 1) * 16 + (pos >> 2) + (pos & 3) * 4;
    d[e] = f2tff(s[k * 128 + n]);
}

__global__ void pack_wconv_kernel(const float* __restrict__ src, float* __restrict__ dst) {
    int e = blockIdx.x * 256 + threadIdx.x;             // 0..262143
    int pos = e & 15, n = (e >> 4) & 127, kcg = e >> 11;
    int k = (kcg >> 1) * 32 + (kcg & 1) * 16 + (pos >> 2) + (pos & 3) * 4;
    dst[e] = f2tff(src[(size_t)k * 128 + n]);
}

// ---------------------------------------------------------------------------
// tf32 GEMM v3: out[M,128] = A[M,128] @ W. W read directly from permuted
// global via LDG.128 (no W smem). A double-buffered, ONE barrier per chunk.
// BM=128, 8 warps x 16 rows x full 128 cols.
// ---------------------------------------------------------------------------
__device__ __forceinline__ void gemm_body(const float* __restrict__ A,
                                          const float* __restrict__ Wp,
                                          float* __restrict__ out, int m0, int tid) {
    __shared__ float sA[2][4096];     // [buf][kg][row128][pos16]
    int w = tid >> 5, lane = tid & 31;
    int gid = lane >> 2, tig = lane & 3;
    int lrow = tid >> 3, lc4 = tid & 7;     // A loader coords (4 float4/thread)

    float oacc[16][4];
#pragma unroll
    for (int i = 0; i < 16; i++)
#pragma unroll
        for (int j = 0; j < 4; j++) oacc[i][j] = 0.f;

    float4 av[4];
#pragma unroll
    for (int i = 0; i < 4; i++)
        av[i] = *(const float4*)&A[(size_t)(m0 + lrow + (i << 5)) * 128 + (lc4 << 2)];
#pragma unroll
    for (int i = 0; i < 4; i++) {
        float4 a = av[i];
        a.x = f2tff(a.x); a.y = f2tff(a.y); a.z = f2tff(a.z); a.w = f2tff(a.w);
        sts_perm(sA[0], 128, lrow + (i << 5), lc4, a);
    }
    __syncthreads();

#pragma unroll
    for (int kc = 0; kc < 4; kc++) {
        int cur = kc & 1;
        if (kc < 3) {
#pragma unroll
            for (int i = 0; i < 4; i++)
                av[i] = *(const float4*)&A[(size_t)(m0 + lrow + (i << 5)) * 128 + ((kc + 1) << 5) + (lc4 << 2)];
        }
#pragma unroll
        for (int kg = 0; kg < 2; kg++) {
            const float* pa = &sA[cur][kg * 2048 + (w * 16 + gid) * 16 + (tig << 2)];
            float4 alo = *(const float4*)pa;
            float4 ahi = *(const float4*)(pa + 128);
            unsigned a0 = __float_as_uint(alo.x), a1 = __float_as_uint(ahi.x);
            unsigned a2 = __float_as_uint(alo.y), a3 = __float_as_uint(ahi.y);
            unsigned c0 = __float_as_uint(alo.z), c1 = __float_as_uint(ahi.z);
            unsigned c2 = __float_as_uint(alo.w), c3 = __float_as_uint(ahi.w);
            const float* wb = Wp + ((size_t)(kc * 2 + kg) * 128 + gid) * 16 + (tig << 2);
#pragma unroll
            for (int nt = 0; nt < 16; nt++) {
                float4 bv = *(const float4*)(wb + nt * 128);
                mma_tf32(oacc[nt][0], oacc[nt][1], oacc[nt][2], oacc[nt][3],
                         a0, a1, a2, a3, __float_as_uint(bv.x), __float_as_uint(bv.y));
                mma_tf32(oacc[nt][0], oacc[nt][1], oacc[nt][2], oacc[nt][3],
                         c0, c1, c2, c3, __float_as_uint(bv.z), __float_as_uint(bv.w));
            }
        }
        if (kc < 3) {
#pragma unroll
            for (int i = 0; i < 4; i++) {
                float4 a = av[i];
                a.x = f2tff(a.x); a.y = f2tff(a.y); a.z = f2tff(a.z); a.w = f2tff(a.w);
                sts_perm(sA[1 - cur], 128, lrow + (i << 5), lc4, a);
            }
            __syncthreads();
        }
    }

    size_t r0 = (size_t)(m0 + w * 16 + gid) * 128;
    size_t r1 = r0 + 8 * 128;
#pragma unroll
    for (int nt = 0; nt < 16; nt++) {
        int c = nt * 8 + 2 * tig;
        *(float2*)&out[r0 + c] = make_float2(oacc[nt][0], oacc[nt][1]);
        *(float2*)&out[r1 + c] = make_float2(oacc[nt][2], oacc[nt][3]);
    }
}

__global__ __launch_bounds__(256)
void gemm_tf32_kernel(const float* __restrict__ A, const float* __restrict__ Wp,
                      float* __restrict__ out) {
    gemm_body(A, Wp, out, blockIdx.x << 7, threadIdx.x);
}

// K and V projections in one launch: grid (M/128, 2)
__global__ __launch_bounds__(256)
void gemm_tf32_dual_kernel(const float* __restrict__ A,
                           const float* __restrict__ Wpk, const float* __restrict__ Wpv,
                           float* __restrict__ outk, float* __restrict__ outv) {
    const float* Wp = blockIdx.y ? Wpv : Wpk;
    float*      out = blockIdx.y ? outv : outk;
    gemm_body(A, Wp, out, blockIdx.x << 7, threadIdx.x);
}

// ---------------------------------------------------------------------------
// Conv v3: split-K x4 (blockIdx.y = kh). Each block: 32 rows x 128 cols over
// k in [kh*512, kh*512+512) = 16 chunks of 32. W direct from permuted global,
// A double-buffered, one barrier per chunk. Writes fp32 partials (no bias).
// ---------------------------------------------------------------------------
__global__ __launch_bounds__(256)
void conv_part_kernel(const float* __restrict__ x, const float* __restrict__ Wp,
                      float* __restrict__ cpart) {
    __shared__ float sA[2][1024];     // [buf][kg][row32][pos16]
    int m0 = blockIdx.x << 5;
    int kz = blockIdx.y;              // = kh
    int tid = threadIdx.x;
    int w = tid >> 5, lane = tid & 31;
    int gid = lane >> 2, tig = lane & 3;
    int rg = w & 1, cg = w >> 1;

    int lrow = tid >> 3, lc4 = tid & 7;     // A loader (1 float4/thread)
    int am = m0 + lrow;
    int ab = am >> 10, apos = am & 1023, aoh = apos >> 5, aow = apos & 31;
    // pixel row for this block's kh: x[ab][aoh*4+kz][aow*4+kw][ci]
    const float* abase = x + ((size_t)((ab * 128 + (aoh << 2) + kz) * 128 + (aow << 2))) * 128;

    float oacc[4][4];
#pragma unroll
    for (int i = 0; i < 4; i++)
#pragma unroll
        for (int j = 0; j < 4; j++) oacc[i][j] = 0.f;

    // chunk cc: local k-chunk; kw = cc>>2, ci0 = (cc&3)*32
    float4 av = *(const float4*)(abase + (lc4 << 2));    // cc=0: kw=0, ci0=0
    {
        float4 a = av;
        a.x = f2tff(a.x); a.y = f2tff(a.y); a.z = f2tff(a.z); a.w = f2tff(a.w);
        sts_perm(sA[0], 32, lrow, lc4, a);
    }
    __syncthreads();

#pragma unroll 1
    for (int cc = 0; cc < 16; cc++) {
        int cur = cc & 1;
        if (cc < 15) {
            int nc = cc + 1;
            int kw = nc >> 2, ci0 = (nc & 3) << 5;
            av = *(const float4*)(abase + (size_t)kw * 128 + ci0 + (lc4 << 2));
        }
        int kcg0 = (kz * 16 + cc) * 2;     // global chunk * 2
#pragma unroll
        for (int kg = 0; kg < 2; kg++) {
            const float* pa = &sA[cur][kg * 512 + (rg * 16 + gid) * 16 + (tig << 2)];
            float4 alo = *(const float4*)pa;
            float4 ahi = *(const float4*)(pa + 128);
            unsigned a0 = __float_as_uint(alo.x), a1 = __float_as_uint(ahi.x);
            unsigned a2 = __float_as_uint(alo.y), a3 = __float_as_uint(ahi.y);
            unsigned c0 = __float_as_uint(alo.z), c1 = __float_as_uint(ahi.z);
            unsigned c2 = __float_as_uint(alo.w), c3 = __float_as_uint(ahi.w);
            const float* wb = Wp + ((size_t)(kcg0 + kg) * 128 + cg * 32 + gid) * 16 + (tig << 2);
#pragma unroll
            for (int nt = 0; nt < 4; nt++) {
                float4 bv = *(const float4*)(wb + nt * 128);
                mma_tf32(oacc[nt][0], oacc[nt][1], oacc[nt][2], oacc[nt][3],
                         a0, a1, a2, a3, __float_as_uint(bv.x), __float_as_uint(bv.y));
                mma_tf32(oacc[nt][0], oacc[nt][1], oacc[nt][2], oacc[nt][3],
                         c0, c1, c2, c3, __float_as_uint(bv.z), __float_as_uint(bv.w));
            }
        }
        if (cc < 15) {
            float4 a = av;
            a.x = f2tff(a.x); a.y = f2tff(a.y); a.z = f2tff(a.z); a.w = f2tff(a.w);
            sts_perm(sA[1 - cur], 32, lrow, lc4, a);
            __syncthreads();
        }
    }

    float* pb = cpart + (size_t)kz * MCONV * 128;
    size_t r0 = (size_t)(m0 + rg * 16 + gid) * 128;
    size_t r1 = r0 + 8 * 128;
#pragma unroll
    for (int nt = 0; nt < 4; nt++) {
        int c = cg * 32 + nt * 8 + 2 * tig;
        *(float2*)&pb[r0 + c] = make_float2(oacc[nt][0], oacc[nt][1]);
        *(float2*)&pb[r1 + c] = make_float2(oacc[nt][2], oacc[nt][3]);
    }
}

// ---------------------------------------------------------------------------
// LN combine: xr = LayerNorm(sum_z cpart[z] + bias). grid=4096, block=128.
// ---------------------------------------------------------------------------
__global__ __launch_bounds__(128)
void ln_combine_kernel(const float* __restrict__ cpart, const float* __restrict__ bias,
                       const float* __restrict__ gamma, const float* __restrict__ beta,
                       float* __restrict__ out) {
    __shared__ float ss[4], ssq[4], sMR[2];
    int m = blockIdx.x, c = threadIdx.x;
    int wd = c >> 5, ln = c & 31;
    float v = bias[c];
#pragma unroll
    for (int z = 0; z < 4; z++)
        v += cpart[((size_t)z * MCONV + m) * 128 + c];
    float s = v, sq = v * v;
#pragma unroll
    for (int off = 16; off > 0; off >>= 1) {
        s  += __shfl_xor_sync(0xffffffffu, s, off);
        sq += __shfl_xor_sync(0xffffffffu, sq, off);
    }
    if (ln == 0) { ss[wd] = s; ssq[wd] = sq; }
    __syncthreads();
    if (c == 0) {
        float S = ss[0] + ss[1] + ss[2] + ss[3];
        float Q = ssq[0] + ssq[1] + ssq[2] + ssq[3];
        float mu = S * 0.0078125f;
        float var = Q * 0.0078125f - mu * mu;
        sMR[0] = mu; sMR[1] = rsqrtf(var + 1e-6f);
    }
    __syncthreads();
    out[(size_t)m * 128 + c] = (v - sMR[0]) * sMR[1] * gamma[c] + beta[c];
}

// ---------------------------------------------------------------------------
// tf32 flash attention (R5-validated) + register prefetch of next K/V chunk.
// ---------------------------------------------------------------------------
__global__ __launch_bounds__(256)
void attn_mma_kernel(const float* __restrict__ Q, const float* __restrict__ K,
                     const float* __restrict__ V, float* __restrict__ O) {
    __shared__ float sK[KCH * 68];
    __shared__ float sV[KCH * 72];
    __shared__ float sP[QTILE * 36];

    int b  = blockIdx.z, h = blockIdx.y;
    int n0 = blockIdx.x * QTILE;
    int tid  = threadIdx.x;
    int w    = tid >> 5;
    int lane = tid & 31;
    int gid  = lane >> 2;
    int tig  = lane & 3;

    unsigned qa[8][4];
    {
        const float* qb = Q + ((size_t)(b * NQ + n0 + w * 16)) * C_DIM + h * DH;
#pragma unroll
        for (int ks = 0; ks < 8; ks++) {
            int c = ks * 8 + tig;
            qa[ks][0] = f2tf(qb[(size_t)gid       * C_DIM + c    ] * 0.125f);
            qa[ks][1] = f2tf(qb[(size_t)(gid + 8) * C_DIM + c    ] * 0.125f);
            qa[ks][2] = f2tf(qb[(size_t)gid       * C_DIM + c + 4] * 0.125f);
            qa[ks][3] = f2tf(qb[(size_t)(gid + 8) * C_DIM + c + 4] * 0.125f);
        }
    }

    const float* kb_ = K + (size_t)(b * NKV) * C_DIM + h * DH;
    const float* vb_ = V + (size_t)(b * NKV) * C_DIM + h * DH;
    int lr0 = tid >> 4, lc4 = tid & 15;     // loader rows lr0 and lr0+16

    float oacc[8][4];
#pragma unroll
    for (int i = 0; i < 8; i++)
#pragma unroll
        for (int j = 0; j < 4; j++) oacc[i][j] = 0.f;
    float m0r = -1e30f, m1r = -1e30f, l0 = 0.f, l1 = 0.f;

    // prefetch chunk 0
    float4 pk0, pk1, pv0, pv1;
    {
        size_t g0 = (size_t)lr0 * C_DIM + (lc4 << 2);
        size_t g1 = (size_t)(lr0 + 16) * C_DIM + (lc4 << 2);
        pk0 = *(const float4*)(kb_ + g0); pk1 = *(const float4*)(kb_ + g1);
        pv0 = *(const float4*)(vb_ + g0); pv1 = *(const float4*)(vb_ + g1);
    }

#pragma unroll 1
    for (int kc = 0; kc < NKV / KCH; kc++) {
        __syncthreads();   // prior chunk fully consumed
        {
            float4 t;
            t.x = f2tff(pk0.x); t.y = f2tff(pk0.y); t.z = f2tff(pk0.z); t.w = f2tff(pk0.w);
            *(float4*)&sK[lr0 * 68 + (lc4 << 2)] = t;
            t.x = f2tff(pk1.x); t.y = f2tff(pk1.y); t.z = f2tff(pk1.z); t.w = f2tff(pk1.w);
            *(float4*)&sK[(lr0 + 16) * 68 + (lc4 << 2)] = t;
            t.x = f2tff(pv0.x); t.y = f2tff(pv0.y); t.z = f2tff(pv0.z); t.w = f2tff(pv0.w);
            *(float4*)&sV[lr0 * 72 + (lc4 << 2)] = t;
            t.x = f2tff(pv1.x); t.y = f2tff(pv1.y); t.z = f2tff(pv1.z); t.w = f2tff(pv1.w);
            *(float4*)&sV[(lr0 + 16) * 72 + (lc4 << 2)] = t;
        }
        __syncthreads();
        if (kc < NKV / KCH - 1) {   // prefetch next chunk (overlaps compute)
            size_t g0 = (size_t)((kc + 1) * KCH + lr0) * C_DIM + (lc4 << 2);
            size_t g1 = g0 + 16 * C_DIM;
            pk0 = *(const float4*)(kb_ + g0); pk1 = *(const float4*)(kb_ + g1);
            pv0 = *(const float4*)(vb_ + g0); pv1 = *(const float4*)(vb_ + g1);
        }

        float sacc[4][4];
#pragma unroll
        for (int i = 0; i < 4; i++)
#pragma unroll
            for (int j = 0; j < 4; j++) sacc[i][j] = 0.f;
#pragma unroll
        for (int ks = 0; ks < 8; ks++) {
#pragma unroll
            for (int nt = 0; nt < 4; nt++) {
                unsigned b0 = __float_as_uint(sK[(nt * 8 + gid) * 68 + ks * 8 + tig]);
                unsigned b1 = __float_as_uint(sK[(nt * 8 + gid) * 68 + ks * 8 + tig + 4]);
                mma_tf32(sacc[nt][0], sacc[nt][1], sacc[nt][2], sacc[nt][3],
                         qa[ks][0], qa[ks][1], qa[ks][2], qa[ks][3], b0, b1);
            }
        }

        float cm0 = -1e30f, cm1 = -1e30f;
#pragma unroll
        for (int nt = 0; nt < 4; nt++) {
            cm0 = fmaxf(cm0, fmaxf(sacc[nt][0], sacc[nt][1]));
            cm1 = fmaxf(cm1, fmaxf(sacc[nt][2], sacc[nt][3]));
        }
        cm0 = fmaxf(cm0, __shfl_xor_sync(0xffffffffu, cm0, 1));
        cm0 = fmaxf(cm0, __shfl_xor_sync(0xffffffffu, cm0, 2));
        cm1 = fmaxf(cm1, __shfl_xor_sync(0xffffffffu, cm1, 1));
        cm1 = fmaxf(cm1, __shfl_xor_sync(0xffffffffu, cm1, 2));
        float mn0 = fmaxf(m0r, cm0), mn1 = fmaxf(m1r, cm1);
        float al0 = __expf(m0r - mn0), al1 = __expf(m1r - mn1);
        float ps0 = 0.f, ps1 = 0.f;
        int r0off = (w * 16 + gid) * 36;
        int r1off = (w * 16 + gid + 8) * 36;
#pragma unroll
        for (int nt = 0; nt < 4; nt++) {
            float p0 = __expf(sacc[nt][0] - mn0);
            float p1 = __expf(sacc[nt][1] - mn0);
            float p2 = __expf(sacc[nt][2] - mn1);
            float p3 = __expf(sacc[nt][3] - mn1);
            ps0 += p0 + p1;
            ps1 += p2 + p3;
            int co = nt * 8 + 2 * tig;
            float2 e0, e1;
            e0.x = f2tff(p0); e0.y = f2tff(p1);
            e1.x = f2tff(p2); e1.y = f2tff(p3);
            *(float2*)&sP[r0off + co] = e0;
            *(float2*)&sP[r1off + co] = e1;
        }
        ps0 += __shfl_xor_sync(0xffffffffu, ps0, 1);
        ps0 += __shfl_xor_sync(0xffffffffu, ps0, 2);
        ps1 += __shfl_xor_sync(0xffffffffu, ps1, 1);
        ps1 += __shfl_xor_sync(0xffffffffu, ps1, 2);
        l0 = l0 * al0 + ps0;  m0r = mn0;
        l1 = l1 * al1 + ps1;  m1r = mn1;
#pragma unroll
        for (int nt = 0; nt < 8; nt++) {
            oacc[nt][0] *= al0; oacc[nt][1] *= al0;
            oacc[nt][2] *= al1; oacc[nt][3] *= al1;
        }
        __syncwarp();

#pragma unroll
        for (int ks = 0; ks < 4; ks++) {
            unsigned a0 = __float_as_uint(sP[r0off + ks * 8 + tig]);
            unsigned a1 = __float_as_uint(sP[r1off + ks * 8 + tig]);
            unsigned a2 = __float_as_uint(sP[r0off + ks * 8 + tig + 4]);
            unsigned a3 = __float_as_uint(sP[r1off + ks * 8 + tig + 4]);
#pragma unroll
            for (int nt = 0; nt < 8; nt++) {
                unsigned b0 = __float_as_uint(sV[(ks * 8 + tig)     * 72 + nt * 8 + gid]);
                unsigned b1 = __float_as_uint(sV[(ks * 8 + tig + 4) * 72 + nt * 8 + gid]);
                mma_tf32(oacc[nt][0], oacc[nt][1], oacc[nt][2], oacc[nt][3],
                         a0, a1, a2, a3, b0, b1);
            }
        }
    }

    float inv0 = 1.f / l0, inv1 = 1.f / l1;
    float* ob = O + ((size_t)(b * NQ + n0 + w * 16)) * C_DIM + h * DH;
#pragma unroll
    for (int nt = 0; nt < 8; nt++) {
        int d = nt * 8 + 2 * tig;
        float2 r0v, r1v;
        r0v.x = oacc[nt][0] * inv0; r0v.y = oacc[nt][1] * inv0;
        r1v.x = oacc[nt][2] * inv1; r1v.y = oacc[nt][3] * inv1;
        *(float2*)(ob + (size_t)gid       * C_DIM + d) = r0v;
        *(float2*)(ob + (size_t)(gid + 8) * C_DIM + d) = r1v;
    }
}

// ---------------------------------------------------------------------------
// Launch. Inputs: x, Wq, Wk, Wv, Wproj, sr_kernel, sr_bias, gamma, beta.
// ---------------------------------------------------------------------------
extern "C" void kernel_launch(void* const* d_in, const int* in_sizes, int n_in,
                              void* d_out, int out_size) {
    const float* x     = (const float*)d_in[0];
    const float* Wq    = (const float*)d_in[1];
    const float* Wk    = (const float*)d_in[2];
    const float* Wv    = (const float*)d_in[3];
    const float* Wp    = (const float*)d_in[4];
    const float* Wsr   = (const float*)d_in[5];
    const float* bias  = (const float*)d_in[6];
    const float* gamma = (const float*)d_in[7];
    const float* beta  = (const float*)d_in[8];

    float *q, *xr, *k, *v, *ao, *wtq, *wtk, *wtv, *wtp, *wct, *cpart;
    cudaGetSymbolAddress((void**)&q,     g_q);
    cudaGetSymbolAddress((void**)&xr,    g_xr);
    cudaGetSymbolAddress((void**)&k,     g_k);
    cudaGetSymbolAddress((void**)&v,     g_v);
    cudaGetSymbolAddress((void**)&ao,    g_ao);
    cudaGetSymbolAddress((void**)&wtq,   g_wtq);
    cudaGetSymbolAddress((void**)&wtk,   g_wtk);
    cudaGetSymbolAddress((void**)&wtv,   g_wtv);
    cudaGetSymbolAddress((void**)&wtp,   g_wtp);
    cudaGetSymbolAddress((void**)&wct,   g_wct);
    cudaGetSymbolAddress((void**)&cpart, g_cpart);

    pack_w4_kernel<<<256, 256>>>(Wq, Wk, Wv, Wp, wtq, wtk, wtv, wtp);
    pack_wconv_kernel<<<1024, 256>>>(Wsr, wct);

    gemm_tf32_kernel<<<(BATCH * NQ) / 128, 256>>>(x, wtq, q);                  // Q proj
    conv_part_kernel<<<dim3(MCONV / 32, 4), 256>>>(x, wct, cpart);             // SR conv
    ln_combine_kernel<<<MCONV, 128>>>(cpart, bias, gamma, beta, xr);           // +bias+LN
    gemm_tf32_dual_kernel<<<dim3((BATCH * NKV) / 128, 2), 256>>>(xr, wtk, wtv, k, v);
    attn_mma_kernel<<<dim3(NQ / QTILE, HEADS, BATCH), 256>>>(q, k, v, ao);     // attention
    gemm_tf32_kernel<<<(BATCH * NQ) / 128, 256>>>(ao, wtp, (float*)d_out);     // out proj
}

// round 11
// speedup vs baseline: 1.2808x; 1.0734x over previous
#include <cuda_runtime.h>
#include <math.h>

// ---------------------------------------------------------------------------
// Problem constants: B=4, N=16384 (H=W=128), C=128, HEADS=2, dh=64, SR=4
// ---------------------------------------------------------------------------
#define BATCH   4
#define NQ      16384
#define C_DIM   128
#define HEADS   2
#define DH      64
#define NKV     1024
#define QTILE   128
#define KCH     32
#define KCONV   2048
#define MCONV   (BATCH * NKV)     // 4096

// Scratch (allocation-free rule: __device__ globals)
__device__ float g_xr   [BATCH * NKV * C_DIM];
__device__ float g_k    [BATCH * NKV * C_DIM];
__device__ float g_v    [BATCH * NKV * C_DIM];
__device__ float g_ao   [BATCH * NQ  * C_DIM];
__device__ float g_cpart[4 * MCONV * C_DIM];      // conv split-K partials
// Pre-permuted tf32 weights, fragment-ready layout:
//   [kcg][n][pos16],  kcg = kc*2+kg,  k = kc*32 + kg*16 + ((pos>>2) + (pos&3)*4)
__device__ float g_wtq[C_DIM * C_DIM];
__device__ float g_wtk[C_DIM * C_DIM];
__device__ float g_wtv[C_DIM * C_DIM];
__device__ float g_wtp[C_DIM * C_DIM];
__device__ float g_wct[C_DIM * KCONV];

// ---------------------------------------------------------------------------
// tf32 helpers (fragment mappings validated R5-R10)
// ---------------------------------------------------------------------------
__device__ __forceinline__ unsigned f2tf(float x) {
    unsigned r;
    asm("cvt.rna.tf32.f32 %0, %1;" : "=r"(r) : "f"(x));
    return r;
}
__device__ __forceinline__ float f2tff(float x) {
    return __uint_as_float(f2tf(x));
}
__device__ __forceinline__ void mma_tf32(float& d0, float& d1, float& d2, float& d3,
                                         unsigned a0, unsigned a1, unsigned a2, unsigned a3,
                                         unsigned b0, unsigned b1) {
    asm volatile(
        "mma.sync.aligned.m16n8k8.row.col.f32.tf32.tf32.f32 "
        "{%0,%1,%2,%3},{%4,%5,%6,%7},{%8,%9},{%0,%1,%2,%3};"
        : "+f"(d0), "+f"(d1), "+f"(d2), "+f"(d3)
        : "r"(a0), "r"(a1), "r"(a2), "r"(a3), "r"(b0), "r"(b1));
}

// Permuted scatter-store for activations: chunk layout [kg][row][pos16],
// pos(k) = (k&3)*4 + (k>>2) within a 16-k group (4x4 transpose, involution).
__device__ __forceinline__ void sts_perm(float* s, int rows16, int row, int c4, float4 v) {
    float* base = s + ((c4 >> 2) * rows16 * 16) + row * 16 + (c4 & 3);
    base[0] = v.x; base[4] = v.y; base[8] = v.z; base[12] = v.w;
}

// ---------------------------------------------------------------------------
// Weight pack kernels: src [K][128] -> permuted fragment layout, tf32.
// ---------------------------------------------------------------------------
__global__ void pack_w4_kernel(const float* __restrict__ s0, const float* __restrict__ s1,
                               const float* __restrict__ s2, const float* __restrict__ s3,
                               float* __restrict__ d0, float* __restrict__ d1,
                               float* __restrict__ d2, float* __restrict__ d3) {
    int id = blockIdx.x * 256 + threadIdx.x;            // 0..65535
    int mat = id >> 14, e = id & 16383;
    const float* s = (mat == 0) ? s0 : (mat == 1) ? s1 : (mat == 2) ? s2 : s3;
    float*       d = (mat == 0) ? d0 : (mat == 1) ? d1 : (mat == 2) ? d2 : d3;
    int pos = e & 15, n = (e >> 4) & 127, kcg = e >> 11;
    int k = (kcg >> 1) * 32 + (kcg & 1) * 16 + (pos >> 2) + (pos & 3) * 4;
    d[e] = f2tff(s[k * 128 + n]);
}

__global__ void pack_wconv_kernel(const float* __restrict__ src, float* __restrict__ dst) {
    int e = blockIdx.x * 256 + threadIdx.x;             // 0..262143
    int pos = e & 15, n = (e >> 4) & 127, kcg = e >> 11;
    int k = (kcg >> 1) * 32 + (kcg & 1) * 16 + (pos >> 2) + (pos & 3) * 4;
    dst[e] = f2tff(src[(size_t)k * 128 + n]);
}

// ---------------------------------------------------------------------------
// tf32 GEMM BM=64: out[M,128] = A[M,128] @ W (Wp permuted, LDG.128 direct).
// 8 warps = 4 M-groups (16 rows) x 2 N-halves (64 cols). ~4 blocks/SM.
// ---------------------------------------------------------------------------
__device__ __forceinline__ void gemm64_body(const float* __restrict__ A,
                                            const float* __restrict__ Wp,
                                            float* __restrict__ out, size_t m0) {
    __shared__ float sA[2][2048];     // [buf][kg][row64][pos16]
    int tid = threadIdx.x;
    int w = tid >> 5, lane = tid & 31;
    int gid = lane >> 2, tig = lane & 3;
    int mg = w & 3, ng = w >> 2;
    int lrow = tid >> 2, lc4a = (tid & 3) << 1;   // 2 float4/thread

    float oacc[8][4];
#pragma unroll
    for (int i = 0; i < 8; i++)
#pragma unroll
        for (int j = 0; j < 4; j++) oacc[i][j] = 0.f;

    float4 av[2];
    av[0] = *(const float4*)&A[(m0 + lrow) * 128 + (lc4a << 2)];
    av[1] = *(const float4*)&A[(m0 + lrow) * 128 + ((lc4a + 1) << 2)];
#pragma unroll
    for (int i = 0; i < 2; i++) {
        float4 a = av[i];
        a.x = f2tff(a.x); a.y = f2tff(a.y); a.z = f2tff(a.z); a.w = f2tff(a.w);
        sts_perm(sA[0], 64, lrow, lc4a + i, a);
    }
    __syncthreads();

#pragma unroll
    for (int kc = 0; kc < 4; kc++) {
        int cur = kc & 1;
        if (kc < 3) {
            av[0] = *(const float4*)&A[(m0 + lrow) * 128 + ((kc + 1) << 5) + (lc4a << 2)];
            av[1] = *(const float4*)&A[(m0 + lrow) * 128 + ((kc + 1) << 5) + ((lc4a + 1) << 2)];
        }
#pragma unroll
        for (int kg = 0; kg < 2; kg++) {
            const float* pa = &sA[cur][kg * 1024 + (mg * 16 + gid) * 16 + (tig << 2)];
            float4 alo = *(const float4*)pa;
            float4 ahi = *(const float4*)(pa + 128);
            unsigned a0 = __float_as_uint(alo.x), a1 = __float_as_uint(ahi.x);
            unsigned a2 = __float_as_uint(alo.y), a3 = __float_as_uint(ahi.y);
            unsigned c0 = __float_as_uint(alo.z), c1 = __float_as_uint(ahi.z);
            unsigned c2 = __float_as_uint(alo.w), c3 = __float_as_uint(ahi.w);
            const float* wb = Wp + ((size_t)(kc * 2 + kg) * 128 + ng * 64 + gid) * 16 + (tig << 2);
#pragma unroll
            for (int nt = 0; nt < 8; nt++) {
                float4 bv = *(const float4*)(wb + nt * 128);
                mma_tf32(oacc[nt][0], oacc[nt][1], oacc[nt][2], oacc[nt][3],
                         a0, a1, a2, a3, __float_as_uint(bv.x), __float_as_uint(bv.y));
                mma_tf32(oacc[nt][0], oacc[nt][1], oacc[nt][2], oacc[nt][3],
                         c0, c1, c2, c3, __float_as_uint(bv.z), __float_as_uint(bv.w));
            }
        }
        if (kc < 3) {
#pragma unroll
            for (int i = 0; i < 2; i++) {
                float4 a = av[i];
                a.x = f2tff(a.x); a.y = f2tff(a.y); a.z = f2tff(a.z); a.w = f2tff(a.w);
                sts_perm(sA[1 - cur], 64, lrow, lc4a + i, a);
            }
            __syncthreads();
        }
    }

    size_t r0 = (m0 + mg * 16 + gid) * 128;
    size_t r1 = r0 + 8 * 128;
#pragma unroll
    for (int nt = 0; nt < 8; nt++) {
        int c = ng * 64 + nt * 8 + 2 * tig;
        *(float2*)&out[r0 + c] = make_float2(oacc[nt][0], oacc[nt][1]);
        *(float2*)&out[r1 + c] = make_float2(oacc[nt][2], oacc[nt][3]);
    }
}

__global__ __launch_bounds__(256)
void gemm64_kernel(const float* __restrict__ A, const float* __restrict__ Wp,
                   float* __restrict__ out) {
    gemm64_body(A, Wp, out, (size_t)blockIdx.x << 6);
}

__global__ __launch_bounds__(256)
void gemm64_dual_kernel(const float* __restrict__ A,
                        const float* __restrict__ Wpk, const float* __restrict__ Wpv,
                        float* __restrict__ outk, float* __restrict__ outv) {
    gemm64_body(A, blockIdx.y ? Wpv : Wpk, blockIdx.y ? outv : outk,
                (size_t)blockIdx.x << 6);
}

// ---------------------------------------------------------------------------
// Conv split-K x4 (blockIdx.y = kh): unchanged from R10 (validated, 37us).
// ---------------------------------------------------------------------------
__global__ __launch_bounds__(256)
void conv_part_kernel(const float* __restrict__ x, const float* __restrict__ Wp,
                      float* __restrict__ cpart) {
    __shared__ float sA[2][1024];
    int m0 = blockIdx.x << 5;
    int kz = blockIdx.y;
    int tid = threadIdx.x;
    int w = tid >> 5, lane = tid & 31;
    int gid = lane >> 2, tig = lane & 3;
    int rg = w & 1, cg = w >> 1;

    int lrow = tid >> 3, lc4 = tid & 7;
    int am = m0 + lrow;
    int ab = am >> 10, apos = am & 1023, aoh = apos >> 5, aow = apos & 31;
    const float* abase = x + ((size_t)((ab * 128 + (aoh << 2) + kz) * 128 + (aow << 2))) * 128;

    float oacc[4][4];
#pragma unroll
    for (int i = 0; i < 4; i++)
#pragma unroll
        for (int j = 0; j < 4; j++) oacc[i][j] = 0.f;

    float4 av = *(const float4*)(abase + (lc4 << 2));
    {
        float4 a = av;
        a.x = f2tff(a.x); a.y = f2tff(a.y); a.z = f2tff(a.z); a.w = f2tff(a.w);
        sts_perm(sA[0], 32, lrow, lc4, a);
    }
    __syncthreads();

#pragma unroll 1
    for (int cc = 0; cc < 16; cc++) {
        int cur = cc & 1;
        if (cc < 15) {
            int nc = cc + 1;
            int kw = nc >> 2, ci0 = (nc & 3) << 5;
            av = *(const float4*)(abase + (size_t)kw * 128 + ci0 + (lc4 << 2));
        }
        int kcg0 = (kz * 16 + cc) * 2;
#pragma unroll
        for (int kg = 0; kg < 2; kg++) {
            const float* pa = &sA[cur][kg * 512 + (rg * 16 + gid) * 16 + (tig << 2)];
            float4 alo = *(const float4*)pa;
            float4 ahi = *(const float4*)(pa + 128);
            unsigned a0 = __float_as_uint(alo.x), a1 = __float_as_uint(ahi.x);
            unsigned a2 = __float_as_uint(alo.y), a3 = __float_as_uint(ahi.y);
            unsigned c0 = __float_as_uint(alo.z), c1 = __float_as_uint(ahi.z);
            unsigned c2 = __float_as_uint(alo.w), c3 = __float_as_uint(ahi.w);
            const float* wb = Wp + ((size_t)(kcg0 + kg) * 128 + cg * 32 + gid) * 16 + (tig << 2);
#pragma unroll
            for (int nt = 0; nt < 4; nt++) {
                float4 bv = *(const float4*)(wb + nt * 128);
                mma_tf32(oacc[nt][0], oacc[nt][1], oacc[nt][2], oacc[nt][3],
                         a0, a1, a2, a3, __float_as_uint(bv.x), __float_as_uint(bv.y));
                mma_tf32(oacc[nt][0], oacc[nt][1], oacc[nt][2], oacc[nt][3],
                         c0, c1, c2, c3, __float_as_uint(bv.z), __float_as_uint(bv.w));
            }
        }
        if (cc < 15) {
            float4 a = av;
            a.x = f2tff(a.x); a.y = f2tff(a.y); a.z = f2tff(a.z); a.w = f2tff(a.w);
            sts_perm(sA[1 - cur], 32, lrow, lc4, a);
            __syncthreads();
        }
    }

    float* pb = cpart + (size_t)kz * MCONV * 128;
    size_t r0 = (size_t)(m0 + rg * 16 + gid) * 128;
    size_t r1 = r0 + 8 * 128;
#pragma unroll
    for (int nt = 0; nt < 4; nt++) {
        int c = cg * 32 + nt * 8 + 2 * tig;
        *(float2*)&pb[r0 + c] = make_float2(oacc[nt][0], oacc[nt][1]);
        *(float2*)&pb[r1 + c] = make_float2(oacc[nt][2], oacc[nt][3]);
    }
}

// ---------------------------------------------------------------------------
// LN combine: xr = LayerNorm(sum_z cpart[z] + bias). grid=4096, block=128.
// ---------------------------------------------------------------------------
__global__ __launch_bounds__(128)
void ln_combine_kernel(const float* __restrict__ cpart, const float* __restrict__ bias,
                       const float* __restrict__ gamma, const float* __restrict__ beta,
                       float* __restrict__ out) {
    __shared__ float ss[4], ssq[4], sMR[2];
    int m = blockIdx.x, c = threadIdx.x;
    int wd = c >> 5, ln = c & 31;
    float v = bias[c];
#pragma unroll
    for (int z = 0; z < 4; z++)
        v += cpart[((size_t)z * MCONV + m) * 128 + c];
    float s = v, sq = v * v;
#pragma unroll
    for (int off = 16; off > 0; off >>= 1) {
        s  += __shfl_xor_sync(0xffffffffu, s, off);
        sq += __shfl_xor_sync(0xffffffffu, sq, off);
    }
    if (ln == 0) { ss[wd] = s; ssq[wd] = sq; }
    __syncthreads();
    if (c == 0) {
        float S = ss[0] + ss[1] + ss[2] + ss[3];
        float Q = ssq[0] + ssq[1] + ssq[2] + ssq[3];
        float mu = S * 0.0078125f;
        float var = Q * 0.0078125f - mu * mu;
        sMR[0] = mu; sMR[1] = rsqrtf(var + 1e-6f);
    }
    __syncthreads();
    out[(size_t)m * 128 + c] = (v - sMR[0]) * sMR[1] * gamma[c] + beta[c];
}

// ---------------------------------------------------------------------------
// Fused Qproj + tf32 flash attention.
// Prologue: Q_tile = x_tile(128x128) @ Wq[:, h*64:h*64+64] via mma (each
// (b,h,tile) block computes a disjoint slice of Qproj -> zero redundancy),
// parked in smem stride-68 layout, then loaded into qa fragments.
// Mainloop: identical to the R10-validated kernel.
// smem union: prologue staging (8192 f) and sQ (8704 f) alias mainloop
// sK|sV|sP (9088 f total); lifetimes are disjoint (syncs between phases).
// ---------------------------------------------------------------------------
__global__ __launch_bounds__(256)
void attn_fused_kernel(const float* __restrict__ x, const float* __restrict__ Wqp,
                       const float* __restrict__ K, const float* __restrict__ V,
                       float* __restrict__ O) {
    __shared__ float smemU[9088];
    float* sK = smemU;             // 32*68 = 2176
    float* sV = smemU + 2176;      // 32*72 = 2304
    float* sP = smemU + 4480;      // 128*36 = 4608
    float* sSt = smemU;            // prologue staging [2][4096... uses 0..8191
    float* sQ  = smemU;            // prologue Q park [128][68] = 8704

    int b  = blockIdx.z, h = blockIdx.y;
    int n0 = blockIdx.x * QTILE;
    int tid  = threadIdx.x;
    int w    = tid >> 5;
    int lane = tid & 31;
    int gid  = lane >> 2;
    int tig  = lane & 3;

    // ===== PROLOGUE: Q = x_tile @ Wq[:, h*64 .. h*64+63] =====
    {
        const float* A = x + ((size_t)(b * NQ + n0)) * C_DIM;
        int lrow = tid >> 3, lc4 = tid & 7;    // 4 float4/thread
        float qc[8][4];
#pragma unroll
        for (int i = 0; i < 8; i++)
#pragma unroll
            for (int j = 0; j < 4; j++) qc[i][j] = 0.f;

        float4 av[4];
#pragma unroll
        for (int i = 0; i < 4; i++)
            av[i] = *(const float4*)&A[(size_t)(lrow + (i << 5)) * 128 + (lc4 << 2)];
#pragma unroll
        for (int i = 0; i < 4; i++) {
            float4 a = av[i];
            a.x = f2tff(a.x); a.y = f2tff(a.y); a.z = f2tff(a.z); a.w = f2tff(a.w);
            sts_perm(sSt, 128, lrow + (i << 5), lc4, a);     // buf0 = sSt[0..4095]
        }
        __syncthreads();

#pragma unroll
        for (int kc = 0; kc < 4; kc++) {
            int cur = kc & 1;
            if (kc < 3) {
#pragma unroll
                for (int i = 0; i < 4; i++)
                    av[i] = *(const float4*)&A[(size_t)(lrow + (i << 5)) * 128 + ((kc + 1) << 5) + (lc4 << 2)];
            }
#pragma unroll
            for (int kg = 0; kg < 2; kg++) {
                const float* pa = &sSt[cur * 4096 + kg * 2048 + (w * 16 + gid) * 16 + (tig << 2)];
                float4 alo = *(const float4*)pa;
                float4 ahi = *(const float4*)(pa + 128);
                unsigned a0 = __float_as_uint(alo.x), a1 = __float_as_uint(ahi.x);
                unsigned a2 = __float_as_uint(alo.y), a3 = __float_as_uint(ahi.y);
                unsigned c0 = __float_as_uint(alo.z), c1 = __float_as_uint(ahi.z);
                unsigned c2 = __float_as_uint(alo.w), c3 = __float_as_uint(ahi.w);
                const float* wb = Wqp + ((size_t)(kc * 2 + kg) * 128 + h * 64 + gid) * 16 + (tig << 2);
#pragma unroll
                for (int nt = 0; nt < 8; nt++) {
                    float4 bv = *(const float4*)(wb + nt * 128);
                    mma_tf32(qc[nt][0], qc[nt][1], qc[nt][2], qc[nt][3],
                             a0, a1, a2, a3, __float_as_uint(bv.x), __float_as_uint(bv.y));
                    mma_tf32(qc[nt][0], qc[nt][1], qc[nt][2], qc[nt][3],
                             c0, c1, c2, c3, __float_as_uint(bv.z), __float_as_uint(bv.w));
                }
            }
            if (kc < 3) {
#pragma unroll
                for (int i = 0; i < 4; i++) {
                    float4 a = av[i];
                    a.x = f2tff(a.x); a.y = f2tff(a.y); a.z = f2tff(a.z); a.w = f2tff(a.w);
                    sts_perm(sSt + (1 - cur) * 4096, 128, lrow + (i << 5), lc4, a);
                }
                __syncthreads();
            }
        }
        __syncthreads();   // all staging reads done before sQ overwrites region

        // park Q (scaled by dh^-0.5 = 0.125, tf32-rounded) at stride 68
        int r0 = w * 16 + gid, r1 = r0 + 8;
#pragma unroll
        for (int nt = 0; nt < 8; nt++) {
            int c = nt * 8 + 2 * tig;
            float2 e0, e1;
            e0.x = f2tff(qc[nt][0] * 0.125f); e0.y = f2tff(qc[nt][1] * 0.125f);
            e1.x = f2tff(qc[nt][2] * 0.125f); e1.y = f2tff(qc[nt][3] * 0.125f);
            *(float2*)&sQ[r0 * 68 + c] = e0;
            *(float2*)&sQ[r1 * 68 + c] = e1;
        }
        __syncthreads();
    }

    // load qa fragments from sQ (rows w*16+gid, +8; conflict-free: 4*gid+tig)
    unsigned qa[8][4];
    {
        int r0 = w * 16 + gid, r1 = r0 + 8;
#pragma unroll
        for (int ks = 0; ks < 8; ks++) {
            int c = ks * 8 + tig;
            qa[ks][0] = __float_as_uint(sQ[r0 * 68 + c]);
            qa[ks][1] = __float_as_uint(sQ[r1 * 68 + c]);
            qa[ks][2] = __float_as_uint(sQ[r0 * 68 + c + 4]);
            qa[ks][3] = __float_as_uint(sQ[r1 * 68 + c + 4]);
        }
    }

    // ===== MAINLOOP (R10-validated) =====
    const float* kb_ = K + (size_t)(b * NKV) * C_DIM + h * DH;
    const float* vb_ = V + (size_t)(b * NKV) * C_DIM + h * DH;
    int lr0 = tid >> 4, lc4m = tid & 15;

    float oacc[8][4];
#pragma unroll
    for (int i = 0; i < 8; i++)
#pragma unroll
        for (int j = 0; j < 4; j++) oacc[i][j] = 0.f;
    float m0r = -1e30f, m1r = -1e30f, l0 = 0.f, l1 = 0.f;

    float4 pk0, pk1, pv0, pv1;
    {
        size_t g0 = (size_t)lr0 * C_DIM + (lc4m << 2);
        size_t g1 = (size_t)(lr0 + 16) * C_DIM + (lc4m << 2);
        pk0 = *(const float4*)(kb_ + g0); pk1 = *(const float4*)(kb_ + g1);
        pv0 = *(const float4*)(vb_ + g0); pv1 = *(const float4*)(vb_ + g1);
    }

#pragma unroll 1
    for (int kc = 0; kc < NKV / KCH; kc++) {
        __syncthreads();   // prior chunk consumed (and, at kc=0, qa loads done)
        {
            float4 t;
            t.x = f2tff(pk0.x); t.y = f2tff(pk0.y); t.z = f2tff(pk0.z); t.w = f2tff(pk0.w);
            *(float4*)&sK[lr0 * 68 + (lc4m << 2)] = t;
            t.x = f2tff(pk1.x); t.y = f2tff(pk1.y); t.z = f2tff(pk1.z); t.w = f2tff(pk1.w);
            *(float4*)&sK[(lr0 + 16) * 68 + (lc4m << 2)] = t;
            t.x = f2tff(pv0.x); t.y = f2tff(pv0.y); t.z = f2tff(pv0.z); t.w = f2tff(pv0.w);
            *(float4*)&sV[lr0 * 72 + (lc4m << 2)] = t;
            t.x = f2tff(pv1.x); t.y = f2tff(pv1.y); t.z = f2tff(pv1.z); t.w = f2tff(pv1.w);
            *(float4*)&sV[(lr0 + 16) * 72 + (lc4m << 2)] = t;
        }
        __syncthreads();
        if (kc < NKV / KCH - 1) {
            size_t g0 = (size_t)((kc + 1) * KCH + lr0) * C_DIM + (lc4m << 2);
            size_t g1 = g0 + 16 * C_DIM;
            pk0 = *(const float4*)(kb_ + g0); pk1 = *(const float4*)(kb_ + g1);
            pv0 = *(const float4*)(vb_ + g0); pv1 = *(const float4*)(vb_ + g1);
        }

        float sacc[4][4];
#pragma unroll
        for (int i = 0; i < 4; i++)
#pragma unroll
            for (int j = 0; j < 4; j++) sacc[i][j] = 0.f;
#pragma unroll
        for (int ks = 0; ks < 8; ks++) {
#pragma unroll
            for (int nt = 0; nt < 4; nt++) {
                unsigned b0 = __float_as_uint(sK[(nt * 8 + gid) * 68 + ks * 8 + tig]);
                unsigned b1 = __float_as_uint(sK[(nt * 8 + gid) * 68 + ks * 8 + tig + 4]);
                mma_tf32(sacc[nt][0], sacc[nt][1], sacc[nt][2], sacc[nt][3],
                         qa[ks][0], qa[ks][1], qa[ks][2], qa[ks][3], b0, b1);
            }
        }

        float cm0 = -1e30f, cm1 = -1e30f;
#pragma unroll
        for (int nt = 0; nt < 4; nt++) {
            cm0 = fmaxf(cm0, fmaxf(sacc[nt][0], sacc[nt][1]));
            cm1 = fmaxf(cm1, fmaxf(sacc[nt][2], sacc[nt][3]));
        }
        cm0 = fmaxf(cm0, __shfl_xor_sync(0xffffffffu, cm0, 1));
        cm0 = fmaxf(cm0, __shfl_xor_sync(0xffffffffu, cm0, 2));
        cm1 = fmaxf(cm1, __shfl_xor_sync(0xffffffffu, cm1, 1));
        cm1 = fmaxf(cm1, __shfl_xor_sync(0xffffffffu, cm1, 2));
        float mn0 = fmaxf(m0r, cm0), mn1 = fmaxf(m1r, cm1);
        float al0 = __expf(m0r - mn0), al1 = __expf(m1r - mn1);
        float ps0 = 0.f, ps1 = 0.f;
        int r0off = (w * 16 + gid) * 36;
        int r1off = (w * 16 + gid + 8) * 36;
#pragma unroll
        for (int nt = 0; nt < 4; nt++) {
            float p0 = __expf(sacc[nt][0] - mn0);
            float p1 = __expf(sacc[nt][1] - mn0);
            float p2 = __expf(sacc[nt][2] - mn1);
            float p3 = __expf(sacc[nt][3] - mn1);
            ps0 += p0 + p1;
            ps1 += p2 + p3;
            int co = nt * 8 + 2 * tig;
            float2 e0, e1;
            e0.x = f2tff(p0); e0.y = f2tff(p1);
            e1.x = f2tff(p2); e1.y = f2tff(p3);
            *(float2*)&sP[r0off + co] = e0;
            *(float2*)&sP[r1off + co] = e1;
        }
        ps0 += __shfl_xor_sync(0xffffffffu, ps0, 1);
        ps0 += __shfl_xor_sync(0xffffffffu, ps0, 2);
        ps1 += __shfl_xor_sync(0xffffffffu, ps1, 1);
        ps1 += __shfl_xor_sync(0xffffffffu, ps1, 2);
        l0 = l0 * al0 + ps0;  m0r = mn0;
        l1 = l1 * al1 + ps1;  m1r = mn1;
#pragma unroll
        for (int nt = 0; nt < 8; nt++) {
            oacc[nt][0] *= al0; oacc[nt][1] *= al0;
            oacc[nt][2] *= al1; oacc[nt][3] *= al1;
        }
        __syncwarp();

#pragma unroll
        for (int ks = 0; ks < 4; ks++) {
            unsigned a0 = __float_as_uint(sP[r0off + ks * 8 + tig]);
            unsigned a1 = __float_as_uint(sP[r1off + ks * 8 + tig]);
            unsigned a2 = __float_as_uint(sP[r0off + ks * 8 + tig + 4]);
            unsigned a3 = __float_as_uint(sP[r1off + ks * 8 + tig + 4]);
#pragma unroll
            for (int nt = 0; nt < 8; nt++) {
                unsigned b0 = __float_as_uint(sV[(ks * 8 + tig)     * 72 + nt * 8 + gid]);
                unsigned b1 = __float_as_uint(sV[(ks * 8 + tig + 4) * 72 + nt * 8 + gid]);
                mma_tf32(oacc[nt][0], oacc[nt][1], oacc[nt][2], oacc[nt][3],
                         a0, a1, a2, a3, b0, b1);
            }
        }
    }

    float inv0 = 1.f / l0, inv1 = 1.f / l1;
    float* ob = O + ((size_t)(b * NQ + n0 + w * 16)) * C_DIM + h * DH;
#pragma unroll
    for (int nt = 0; nt < 8; nt++) {
        int d = nt * 8 + 2 * tig;
        float2 r0v, r1v;
        r0v.x = oacc[nt][0] * inv0; r0v.y = oacc[nt][1] * inv0;
        r1v.x = oacc[nt][2] * inv1; r1v.y = oacc[nt][3] * inv1;
        *(float2*)(ob + (size_t)gid       * C_DIM + d) = r0v;
        *(float2*)(ob + (size_t)(gid + 8) * C_DIM + d) = r1v;
    }
}

// ---------------------------------------------------------------------------
// Launch. Inputs: x, Wq, Wk, Wv, Wproj, sr_kernel, sr_bias, gamma, beta.
// ---------------------------------------------------------------------------
extern "C" void kernel_launch(void* const* d_in, const int* in_sizes, int n_in,
                              void* d_out, int out_size) {
    const float* x     = (const float*)d_in[0];
    const float* Wq    = (const float*)d_in[1];
    const float* Wk    = (const float*)d_in[2];
    const float* Wv    = (const float*)d_in[3];
    const float* Wp    = (const float*)d_in[4];
    const float* Wsr   = (const float*)d_in[5];
    const float* bias  = (const float*)d_in[6];
    const float* gamma = (const float*)d_in[7];
    const float* beta  = (const float*)d_in[8];

    float *xr, *k, *v, *ao, *wtq, *wtk, *wtv, *wtp, *wct, *cpart;
    cudaGetSymbolAddress((void**)&xr,    g_xr);
    cudaGetSymbolAddress((void**)&k,     g_k);
    cudaGetSymbolAddress((void**)&v,     g_v);
    cudaGetSymbolAddress((void**)&ao,    g_ao);
    cudaGetSymbolAddress((void**)&wtq,   g_wtq);
    cudaGetSymbolAddress((void**)&wtk,   g_wtk);
    cudaGetSymbolAddress((void**)&wtv,   g_wtv);
    cudaGetSymbolAddress((void**)&wtp,   g_wtp);
    cudaGetSymbolAddress((void**)&wct,   g_wct);
    cudaGetSymbolAddress((void**)&cpart, g_cpart);

    pack_w4_kernel<<<256, 256>>>(Wq, Wk, Wv, Wp, wtq, wtk, wtv, wtp);
    pack_wconv_kernel<<<1024, 256>>>(Wsr, wct);

    conv_part_kernel<<<dim3(MCONV / 32, 4), 256>>>(x, wct, cpart);             // SR conv
    ln_combine_kernel<<<MCONV, 128>>>(cpart, bias, gamma, beta, xr);           // +bias+LN
    gemm64_dual_kernel<<<dim3((BATCH * NKV) / 64, 2), 256>>>(xr, wtk, wtv, k, v);
    attn_fused_kernel<<<dim3(NQ / QTILE, HEADS, BATCH), 256>>>(x, wtq, k, v, ao);
    gemm64_kernel<<<(BATCH * NQ) / 64, 256>>>(ao, wtp, (float*)d_out);         // out proj
}

// round 12
// speedup vs baseline: 1.2903x; 1.0075x over previous
#include <cuda_runtime.h>
#include <math.h>

// ---------------------------------------------------------------------------
// Problem constants: B=4, N=16384 (H=W=128), C=128, HEADS=2, dh=64, SR=4
// ---------------------------------------------------------------------------
#define BATCH   4
#define NQ      16384
#define C_DIM   128
#define HEADS   2
#define DH      64
#define NKV     1024
#define QTILE   128
#define KCH     32
#define KCONV   2048
#define MCONV   (BATCH * NKV)     // 4096
#define MQ      (BATCH * NQ)      // 65536

// Scratch (allocation-free rule: __device__ globals)
__device__ float g_xrp  [MCONV * C_DIM];          // xr, fragment-permuted [kcg][m][16]
__device__ float g_k    [BATCH * NKV * C_DIM];    // row-major
__device__ float g_v    [BATCH * NKV * C_DIM];    // row-major
__device__ float g_aop  [MQ * C_DIM];             // attn out, fragment-permuted
__device__ float g_cpart[4 * MCONV * C_DIM];      // conv split-K partials
// Pre-permuted tf32 weights, fragment-ready layout:
//   [kcg][n][pos16],  kcg = kc*2+kg,  k = kc*32 + kg*16 + ((pos>>2) + (pos&3)*4)
__device__ float g_wtq[C_DIM * C_DIM];
__device__ float g_wtk[C_DIM * C_DIM];
__device__ float g_wtv[C_DIM * C_DIM];
__device__ float g_wtp[C_DIM * C_DIM];
__device__ float g_wct[C_DIM * KCONV];

// ---------------------------------------------------------------------------
// tf32 helpers (fragment mappings validated R5-R11)
// ---------------------------------------------------------------------------
__device__ __forceinline__ unsigned f2tf(float x) {
    unsigned r;
    asm("cvt.rna.tf32.f32 %0, %1;" : "=r"(r) : "f"(x));
    return r;
}
__device__ __forceinline__ float f2tff(float x) {
    return __uint_as_float(f2tf(x));
}
__device__ __forceinline__ void mma_tf32(float& d0, float& d1, float& d2, float& d3,
                                         unsigned a0, unsigned a1, unsigned a2, unsigned a3,
                                         unsigned b0, unsigned b1) {
    asm volatile(
        "mma.sync.aligned.m16n8k8.row.col.f32.tf32.tf32.f32 "
        "{%0,%1,%2,%3},{%4,%5,%6,%7},{%8,%9},{%0,%1,%2,%3};"
        : "+f"(d0), "+f"(d1), "+f"(d2), "+f"(d3)
        : "r"(a0), "r"(a1), "r"(a2), "r"(a3), "r"(b0), "r"(b1));
}

// Permutation within a 16-k group (4x4 transpose, involution):
// element with k-in-group kk stored at pos = (kk&3)*4 + (kk>>2).
__device__ __forceinline__ int perm16(int p) { return (p & 3) * 4 + (p >> 2); }

// Permuted scatter-store for activations into smem: chunk layout [kg][row][pos16].
__device__ __forceinline__ void sts_perm(float* s, int rows16, int row, int c4, float4 v) {
    float* base = s + ((c4 >> 2) * rows16 * 16) + row * 16 + (c4 & 3);
    base[0] = v.x; base[4] = v.y; base[8] = v.z; base[12] = v.w;
}

// ---------------------------------------------------------------------------
// Weight pack kernels: src [K][128] -> permuted fragment layout, tf32.
// ---------------------------------------------------------------------------
__global__ void pack_w4_kernel(const float* __restrict__ s0, const float* __restrict__ s1,
                               const float* __restrict__ s2, const float* __restrict__ s3,
                               float* __restrict__ d0, float* __restrict__ d1,
                               float* __restrict__ d2, float* __restrict__ d3) {
    int id = blockIdx.x * 256 + threadIdx.x;            // 0..65535
    int mat = id >> 14, e = id & 16383;
    const float* s = (mat == 0) ? s0 : (mat == 1) ? s1 : (mat == 2) ? s2 : s3;
    float*       d = (mat == 0) ? d0 : (mat == 1) ? d1 : (mat == 2) ? d2 : d3;
    int pos = e & 15, n = (e >> 4) & 127, kcg = e >> 11;
    int k = (kcg >> 1) * 32 + (kcg & 1) * 16 + perm16(pos);
    d[e] = f2tff(s[k * 128 + n]);
}

__global__ void pack_wconv_kernel(const float* __restrict__ src, float* __restrict__ dst) {
    int e = blockIdx.x * 256 + threadIdx.x;             // 0..262143
    int pos = e & 15, n = (e >> 4) & 127, kcg = e >> 11;
    int k = (kcg >> 1) * 32 + (kcg & 1) * 16 + perm16(pos);
    dst[e] = f2tff(src[(size_t)k * 128 + n]);
}

// ---------------------------------------------------------------------------
// Smem-free warp-autonomous GEMM: out[M,128] = Aperm @ Wperm.
// Aperm: [kcg=8][M][16] fragment-ready (tf32 already). No smem, no barriers.
// Block = 8 warps: mg=w&3 (16 rows), ng=w>>2 (64 cols). BM=64 per block.
// ---------------------------------------------------------------------------
__device__ __forceinline__ void gemm_frag_body(const float* __restrict__ Ap,
                                               const float* __restrict__ Wp,
                                               float* __restrict__ out,
                                               size_t M, size_t m0) {
    int tid = threadIdx.x;
    int w = tid >> 5, lane = tid & 31;
    int gid = lane >> 2, tig = lane & 3;
    int mg = w & 3, ng = w >> 2;
    size_t m = m0 + mg * 16 + gid;          // rows m and m+8

    float oacc[8][4];
#pragma unroll
    for (int i = 0; i < 8; i++)
#pragma unroll
        for (int j = 0; j < 4; j++) oacc[i][j] = 0.f;

#pragma unroll
    for (int kcg = 0; kcg < 8; kcg++) {
        const float* ab = Ap + ((size_t)kcg * M + m) * 16 + (tig << 2);
        float4 alo = *(const float4*)ab;
        float4 ahi = *(const float4*)(ab + 128);        // row m+8
        unsigned a0 = __float_as_uint(alo.x), a1 = __float_as_uint(ahi.x);
        unsigned a2 = __float_as_uint(alo.y), a3 = __float_as_uint(ahi.y);
        unsigned c0 = __float_as_uint(alo.z), c1 = __float_as_uint(ahi.z);
        unsigned c2 = __float_as_uint(alo.w), c3 = __float_as_uint(ahi.w);
        const float* wb = Wp + ((size_t)kcg * 128 + ng * 64 + gid) * 16 + (tig << 2);
#pragma unroll
        for (int nt = 0; nt < 8; nt++) {
            float4 bv = *(const float4*)(wb + nt * 128);
            mma_tf32(oacc[nt][0], oacc[nt][1], oacc[nt][2], oacc[nt][3],
                     a0, a1, a2, a3, __float_as_uint(bv.x), __float_as_uint(bv.y));
            mma_tf32(oacc[nt][0], oacc[nt][1], oacc[nt][2], oacc[nt][3],
                     c0, c1, c2, c3, __float_as_uint(bv.z), __float_as_uint(bv.w));
        }
    }

    size_t r0 = m * 128;
    size_t r1 = r0 + 8 * 128;
#pragma unroll
    for (int nt = 0; nt < 8; nt++) {
        int c = ng * 64 + nt * 8 + 2 * tig;
        *(float2*)&out[r0 + c] = make_float2(oacc[nt][0], oacc[nt][1]);
        *(float2*)&out[r1 + c] = make_float2(oacc[nt][2], oacc[nt][3]);
    }
}

__global__ __launch_bounds__(256)
void gemm_frag_kernel(const float* __restrict__ Ap, const float* __restrict__ Wp,
                      float* __restrict__ out) {
    gemm_frag_body(Ap, Wp, out, (size_t)MQ, (size_t)blockIdx.x << 6);
}

__global__ __launch_bounds__(256)
void gemm_frag_dual_kernel(const float* __restrict__ Ap,
                           const float* __restrict__ Wpk, const float* __restrict__ Wpv,
                           float* __restrict__ outk, float* __restrict__ outv) {
    gemm_frag_body(Ap, blockIdx.y ? Wpv : Wpk, blockIdx.y ? outv : outk,
                   (size_t)MCONV, (size_t)blockIdx.x << 6);
}

// ---------------------------------------------------------------------------
// Conv split-K x4 (blockIdx.y = kh): unchanged (R10-validated, 37us).
// ---------------------------------------------------------------------------
__global__ __launch_bounds__(256)
void conv_part_kernel(const float* __restrict__ x, const float* __restrict__ Wp,
                      float* __restrict__ cpart) {
    __shared__ float sA[2][1024];
    int m0 = blockIdx.x << 5;
    int kz = blockIdx.y;
    int tid = threadIdx.x;
    int w = tid >> 5, lane = tid & 31;
    int gid = lane >> 2, tig = lane & 3;
    int rg = w & 1, cg = w >> 1;

    int lrow = tid >> 3, lc4 = tid & 7;
    int am = m0 + lrow;
    int ab = am >> 10, apos = am & 1023, aoh = apos >> 5, aow = apos & 31;
    const float* abase = x + ((size_t)((ab * 128 + (aoh << 2) + kz) * 128 + (aow << 2))) * 128;

    float oacc[4][4];
#pragma unroll
    for (int i = 0; i < 4; i++)
#pragma unroll
        for (int j = 0; j < 4; j++) oacc[i][j] = 0.f;

    float4 av = *(const float4*)(abase + (lc4 << 2));
    {
        float4 a = av;
        a.x = f2tff(a.x); a.y = f2tff(a.y); a.z = f2tff(a.z); a.w = f2tff(a.w);
        sts_perm(sA[0], 32, lrow, lc4, a);
    }
    __syncthreads();

#pragma unroll 1
    for (int cc = 0; cc < 16; cc++) {
        int cur = cc & 1;
        if (cc < 15) {
            int nc = cc + 1;
            int kw = nc >> 2, ci0 = (nc & 3) << 5;
            av = *(const float4*)(abase + (size_t)kw * 128 + ci0 + (lc4 << 2));
        }
        int kcg0 = (kz * 16 + cc) * 2;
#pragma unroll
        for (int kg = 0; kg < 2; kg++) {
            const float* pa = &sA[cur][kg * 512 + (rg * 16 + gid) * 16 + (tig << 2)];
            float4 alo = *(const float4*)pa;
            float4 ahi = *(const float4*)(pa + 128);
            unsigned a0 = __float_as_uint(alo.x), a1 = __float_as_uint(ahi.x);
            unsigned a2 = __float_as_uint(alo.y), a3 = __float_as_uint(ahi.y);
            unsigned c0 = __float_as_uint(alo.z), c1 = __float_as_uint(ahi.z);
            unsigned c2 = __float_as_uint(alo.w), c3 = __float_as_uint(ahi.w);
            const float* wb = Wp + ((size_t)(kcg0 + kg) * 128 + cg * 32 + gid) * 16 + (tig << 2);
#pragma unroll
            for (int nt = 0; nt < 4; nt++) {
                float4 bv = *(const float4*)(wb + nt * 128);
                mma_tf32(oacc[nt][0], oacc[nt][1], oacc[nt][2], oacc[nt][3],
                         a0, a1, a2, a3, __float_as_uint(bv.x), __float_as_uint(bv.y));
                mma_tf32(oacc[nt][0], oacc[nt][1], oacc[nt][2], oacc[nt][3],
                         c0, c1, c2, c3, __float_as_uint(bv.z), __float_as_uint(bv.w));
            }
        }
        if (cc < 15) {
            float4 a = av;
            a.x = f2tff(a.x); a.y = f2tff(a.y); a.z = f2tff(a.z); a.w = f2tff(a.w);
            sts_perm(sA[1 - cur], 32, lrow, lc4, a);
            __syncthreads();
        }
    }

    float* pb = cpart + (size_t)kz * MCONV * 128;
    size_t r0 = (size_t)(m0 + rg * 16 + gid) * 128;
    size_t r1 = r0 + 8 * 128;
#pragma unroll
    for (int nt = 0; nt < 4; nt++) {
        int c = cg * 32 + nt * 8 + 2 * tig;
        *(float2*)&pb[r0 + c] = make_float2(oacc[nt][0], oacc[nt][1]);
        *(float2*)&pb[r1 + c] = make_float2(oacc[nt][2], oacc[nt][3]);
    }
}

// ---------------------------------------------------------------------------
// LN combine: xr = LayerNorm(sum_z cpart[z] + bias), written PERMUTED
// (fragment-ready, tf32) for the smem-free K/V GEMM. grid=4096, block=128.
// ---------------------------------------------------------------------------
__global__ __launch_bounds__(128)
void ln_combine_kernel(const float* __restrict__ cpart, const float* __restrict__ bias,
                       const float* __restrict__ gamma, const float* __restrict__ beta,
                       float* __restrict__ xrp) {
    __shared__ float ss[4], ssq[4], sMR[2];
    int m = blockIdx.x, c = threadIdx.x;
    int wd = c >> 5, ln = c & 31;
    float v = bias[c];
#pragma unroll
    for (int z = 0; z < 4; z++)
        v += cpart[((size_t)z * MCONV + m) * 128 + c];
    float s = v, sq = v * v;
#pragma unroll
    for (int off = 16; off > 0; off >>= 1) {
        s  += __shfl_xor_sync(0xffffffffu, s, off);
        sq += __shfl_xor_sync(0xffffffffu, sq, off);
    }
    if (ln == 0) { ss[wd] = s; ssq[wd] = sq; }
    __syncthreads();
    if (c == 0) {
        float S = ss[0] + ss[1] + ss[2] + ss[3];
        float Q = ssq[0] + ssq[1] + ssq[2] + ssq[3];
        float mu = S * 0.0078125f;
        float var = Q * 0.0078125f - mu * mu;
        sMR[0] = mu; sMR[1] = rsqrtf(var + 1e-6f);
    }
    __syncthreads();
    float r = (v - sMR[0]) * sMR[1] * gamma[c] + beta[c];
    int kcg = c >> 4, pp = perm16(c & 15);
    xrp[((size_t)kcg * MCONV + m) * 16 + pp] = f2tff(r);
}

// ---------------------------------------------------------------------------
// Fused Qproj + tf32 flash attention (R11-validated) with permuted-ao epilogue.
// ---------------------------------------------------------------------------
__global__ __launch_bounds__(256)
void attn_fused_kernel(const float* __restrict__ x, const float* __restrict__ Wqp,
                       const float* __restrict__ K, const float* __restrict__ V,
                       float* __restrict__ AOP) {
    __shared__ float smemU[9088];
    float* sK = smemU;             // 32*68 = 2176
    float* sV = smemU + 2176;      // 32*72 = 2304
    float* sP = smemU + 4480;      // 128*36 = 4608
    float* sSt = smemU;            // prologue staging: 2 x 4096
    float* sQ  = smemU;            // prologue Q park: 128*68 = 8704

    int b  = blockIdx.z, h = blockIdx.y;
    int n0 = blockIdx.x * QTILE;
    int tid  = threadIdx.x;
    int w    = tid >> 5;
    int lane = tid & 31;
    int gid  = lane >> 2;
    int tig  = lane & 3;

    // ===== PROLOGUE: Q = x_tile @ Wq[:, h*64 .. h*64+63] =====
    {
        const float* A = x + ((size_t)(b * NQ + n0)) * C_DIM;
        int lrow = tid >> 3, lc4 = tid & 7;
        float qc[8][4];
#pragma unroll
        for (int i = 0; i < 8; i++)
#pragma unroll
            for (int j = 0; j < 4; j++) qc[i][j] = 0.f;

        float4 av[4];
#pragma unroll
        for (int i = 0; i < 4; i++)
            av[i] = *(const float4*)&A[(size_t)(lrow + (i << 5)) * 128 + (lc4 << 2)];
#pragma unroll
        for (int i = 0; i < 4; i++) {
            float4 a = av[i];
            a.x = f2tff(a.x); a.y = f2tff(a.y); a.z = f2tff(a.z); a.w = f2tff(a.w);
            sts_perm(sSt, 128, lrow + (i << 5), lc4, a);
        }
        __syncthreads();

#pragma unroll
        for (int kc = 0; kc < 4; kc++) {
            int cur = kc & 1;
            if (kc < 3) {
#pragma unroll
                for (int i = 0; i < 4; i++)
                    av[i] = *(const float4*)&A[(size_t)(lrow + (i << 5)) * 128 + ((kc + 1) << 5) + (lc4 << 2)];
            }
#pragma unroll
            for (int kg = 0; kg < 2; kg++) {
                const float* pa = &sSt[cur * 4096 + kg * 2048 + (w * 16 + gid) * 16 + (tig << 2)];
                float4 alo = *(const float4*)pa;
                float4 ahi = *(const float4*)(pa + 128);
                unsigned a0 = __float_as_uint(alo.x), a1 = __float_as_uint(ahi.x);
                unsigned a2 = __float_as_uint(alo.y), a3 = __float_as_uint(ahi.y);
                unsigned c0 = __float_as_uint(alo.z), c1 = __float_as_uint(ahi.z);
                unsigned c2 = __float_as_uint(alo.w), c3 = __float_as_uint(ahi.w);
                const float* wb = Wqp + ((size_t)(kc * 2 + kg) * 128 + h * 64 + gid) * 16 + (tig << 2);
#pragma unroll
                for (int nt = 0; nt < 8; nt++) {
                    float4 bv = *(const float4*)(wb + nt * 128);
                    mma_tf32(qc[nt][0], qc[nt][1], qc[nt][2], qc[nt][3],
                             a0, a1, a2, a3, __float_as_uint(bv.x), __float_as_uint(bv.y));
                    mma_tf32(qc[nt][0], qc[nt][1], qc[nt][2], qc[nt][3],
                             c0, c1, c2, c3, __float_as_uint(bv.z), __float_as_uint(bv.w));
                }
            }
            if (kc < 3) {
#pragma unroll
                for (int i = 0; i < 4; i++) {
                    float4 a = av[i];
                    a.x = f2tff(a.x); a.y = f2tff(a.y); a.z = f2tff(a.z); a.w = f2tff(a.w);
                    sts_perm(sSt + (1 - cur) * 4096, 128, lrow + (i << 5), lc4, a);
                }
                __syncthreads();
            }
        }
        __syncthreads();

        int r0 = w * 16 + gid, r1 = r0 + 8;
#pragma unroll
        for (int nt = 0; nt < 8; nt++) {
            int c = nt * 8 + 2 * tig;
            float2 e0, e1;
            e0.x = f2tff(qc[nt][0] * 0.125f); e0.y = f2tff(qc[nt][1] * 0.125f);
            e1.x = f2tff(qc[nt][2] * 0.125f); e1.y = f2tff(qc[nt][3] * 0.125f);
            *(float2*)&sQ[r0 * 68 + c] = e0;
            *(float2*)&sQ[r1 * 68 + c] = e1;
        }
        __syncthreads();
    }

    unsigned qa[8][4];
    {
        int r0 = w * 16 + gid, r1 = r0 + 8;
#pragma unroll
        for (int ks = 0; ks < 8; ks++) {
            int c = ks * 8 + tig;
            qa[ks][0] = __float_as_uint(sQ[r0 * 68 + c]);
            qa[ks][1] = __float_as_uint(sQ[r1 * 68 + c]);
            qa[ks][2] = __float_as_uint(sQ[r0 * 68 + c + 4]);
            qa[ks][3] = __float_as_uint(sQ[r1 * 68 + c + 4]);
        }
    }

    // ===== MAINLOOP (validated) =====
    const float* kb_ = K + (size_t)(b * NKV) * C_DIM + h * DH;
    const float* vb_ = V + (size_t)(b * NKV) * C_DIM + h * DH;
    int lr0 = tid >> 4, lc4m = tid & 15;

    float oacc[8][4];
#pragma unroll
    for (int i = 0; i < 8; i++)
#pragma unroll
        for (int j = 0; j < 4; j++) oacc[i][j] = 0.f;
    float m0r = -1e30f, m1r = -1e30f, l0 = 0.f, l1 = 0.f;

    float4 pk0, pk1, pv0, pv1;
    {
        size_t g0 = (size_t)lr0 * C_DIM + (lc4m << 2);
        size_t g1 = (size_t)(lr0 + 16) * C_DIM + (lc4m << 2);
        pk0 = *(const float4*)(kb_ + g0); pk1 = *(const float4*)(kb_ + g1);
        pv0 = *(const float4*)(vb_ + g0); pv1 = *(const float4*)(vb_ + g1);
    }

#pragma unroll 1
    for (int kc = 0; kc < NKV / KCH; kc++) {
        __syncthreads();
        {
            float4 t;
            t.x = f2tff(pk0.x); t.y = f2tff(pk0.y); t.z = f2tff(pk0.z); t.w = f2tff(pk0.w);
            *(float4*)&sK[lr0 * 68 + (lc4m << 2)] = t;
            t.x = f2tff(pk1.x); t.y = f2tff(pk1.y); t.z = f2tff(pk1.z); t.w = f2tff(pk1.w);
            *(float4*)&sK[(lr0 + 16) * 68 + (lc4m << 2)] = t;
            t.x = f2tff(pv0.x); t.y = f2tff(pv0.y); t.z = f2tff(pv0.z); t.w = f2tff(pv0.w);
            *(float4*)&sV[lr0 * 72 + (lc4m << 2)] = t;
            t.x = f2tff(pv1.x); t.y = f2tff(pv1.y); t.z = f2tff(pv1.z); t.w = f2tff(pv1.w);
            *(float4*)&sV[(lr0 + 16) * 72 + (lc4m << 2)] = t;
        }
        __syncthreads();
        if (kc < NKV / KCH - 1) {
            size_t g0 = (size_t)((kc + 1) * KCH + lr0) * C_DIM + (lc4m << 2);
            size_t g1 = g0 + 16 * C_DIM;
            pk0 = *(const float4*)(kb_ + g0); pk1 = *(const float4*)(kb_ + g1);
            pv0 = *(const float4*)(vb_ + g0); pv1 = *(const float4*)(vb_ + g1);
        }

        float sacc[4][4];
#pragma unroll
        for (int i = 0; i < 4; i++)
#pragma unroll
            for (int j = 0; j < 4; j++) sacc[i][j] = 0.f;
#pragma unroll
        for (int ks = 0; ks < 8; ks++) {
#pragma unroll
            for (int nt = 0; nt < 4; nt++) {
                unsigned b0 = __float_as_uint(sK[(nt * 8 + gid) * 68 + ks * 8 + tig]);
                unsigned b1 = __float_as_uint(sK[(nt * 8 + gid) * 68 + ks * 8 + tig + 4]);
                mma_tf32(sacc[nt][0], sacc[nt][1], sacc[nt][2], sacc[nt][3],
                         qa[ks][0], qa[ks][1], qa[ks][2], qa[ks][3], b0, b1);
            }
        }

        float cm0 = -1e30f, cm1 = -1e30f;
#pragma unroll
        for (int nt = 0; nt < 4; nt++) {
            cm0 = fmaxf(cm0, fmaxf(sacc[nt][0], sacc[nt][1]));
            cm1 = fmaxf(cm1, fmaxf(sacc[nt][2], sacc[nt][3]));
        }
        cm0 = fmaxf(cm0, __shfl_xor_sync(0xffffffffu, cm0, 1));
        cm0 = fmaxf(cm0, __shfl_xor_sync(0xffffffffu, cm0, 2));
        cm1 = fmaxf(cm1, __shfl_xor_sync(0xffffffffu, cm1, 1));
        cm1 = fmaxf(cm1, __shfl_xor_sync(0xffffffffu, cm1, 2));
        float mn0 = fmaxf(m0r, cm0), mn1 = fmaxf(m1r, cm1);
        float al0 = __expf(m0r - mn0), al1 = __expf(m1r - mn1);
        float ps0 = 0.f, ps1 = 0.f;
        int r0off = (w * 16 + gid) * 36;
        int r1off = (w * 16 + gid + 8) * 36;
#pragma unroll
        for (int nt = 0; nt < 4; nt++) {
            float p0 = __expf(sacc[nt][0] - mn0);
            float p1 = __expf(sacc[nt][1] - mn0);
            float p2 = __expf(sacc[nt][2] - mn1);
            float p3 = __expf(sacc[nt][3] - mn1);
            ps0 += p0 + p1;
            ps1 += p2 + p3;
            int co = nt * 8 + 2 * tig;
            float2 e0, e1;
            e0.x = f2tff(p0); e0.y = f2tff(p1);
            e1.x = f2tff(p2); e1.y = f2tff(p3);
            *(float2*)&sP[r0off + co] = e0;
            *(float2*)&sP[r1off + co] = e1;
        }
        ps0 += __shfl_xor_sync(0xffffffffu, ps0, 1);
        ps0 += __shfl_xor_sync(0xffffffffu, ps0, 2);
        ps1 += __shfl_xor_sync(0xffffffffu, ps1, 1);
        ps1 += __shfl_xor_sync(0xffffffffu, ps1, 2);
        l0 = l0 * al0 + ps0;  m0r = mn0;
        l1 = l1 * al1 + ps1;  m1r = mn1;
#pragma unroll
        for (int nt = 0; nt < 8; nt++) {
            oacc[nt][0] *= al0; oacc[nt][1] *= al0;
            oacc[nt][2] *= al1; oacc[nt][3] *= al1;
        }
        __syncwarp();

#pragma unroll
        for (int ks = 0; ks < 4; ks++) {
            unsigned a0 = __float_as_uint(sP[r0off + ks * 8 + tig]);
            unsigned a1 = __float_as_uint(sP[r1off + ks * 8 + tig]);
            unsigned a2 = __float_as_uint(sP[r0off + ks * 8 + tig + 4]);
            unsigned a3 = __float_as_uint(sP[r1off + ks * 8 + tig + 4]);
#pragma unroll
            for (int nt = 0; nt < 8; nt++) {
                unsigned b0 = __float_as_uint(sV[(ks * 8 + tig)     * 72 + nt * 8 + gid]);
                unsigned b1 = __float_as_uint(sV[(ks * 8 + tig + 4) * 72 + nt * 8 + gid]);
                mma_tf32(oacc[nt][0], oacc[nt][1], oacc[nt][2], oacc[nt][3],
                         a0, a1, a2, a3, b0, b1);
            }
        }
    }

    // ===== EPILOGUE: write permuted fragment-ready ao (tf32-rounded) =====
    float inv0 = 1.f / l0, inv1 = 1.f / l1;
    size_t mrow = (size_t)(b * NQ + n0 + w * 16 + gid);
#pragma unroll
    for (int nt = 0; nt < 8; nt++) {
        int c = h * 64 + nt * 8 + 2 * tig;
        int kcg = c >> 4;
        int pp = perm16(c & 15);
        float* base0 = AOP + ((size_t)kcg * MQ + mrow) * 16;
        float* base1 = base0 + 128;     // row mrow+8
        base0[pp]     = f2tff(oacc[nt][0] * inv0);
        base0[pp + 4] = f2tff(oacc[nt][1] * inv0);
        base1[pp]     = f2tff(oacc[nt][2] * inv1);
        base1[pp + 4] = f2tff(oacc[nt][3] * inv1);
    }
}

// ---------------------------------------------------------------------------
// Launch. Inputs: x, Wq, Wk, Wv, Wproj, sr_kernel, sr_bias, gamma, beta.
// ---------------------------------------------------------------------------
extern "C" void kernel_launch(void* const* d_in, const int* in_sizes, int n_in,
                              void* d_out, int out_size) {
    const float* x     = (const float*)d_in[0];
    const float* Wq    = (const float*)d_in[1];
    const float* Wk    = (const float*)d_in[2];
    const float* Wv    = (const float*)d_in[3];
    const float* Wp    = (const float*)d_in[4];
    const float* Wsr   = (const float*)d_in[5];
    const float* bias  = (const float*)d_in[6];
    const float* gamma = (const float*)d_in[7];
    const float* beta  = (const float*)d_in[8];

    float *xrp, *k, *v, *aop, *wtq, *wtk, *wtv, *wtp, *wct, *cpart;
    cudaGetSymbolAddress((void**)&xrp,   g_xrp);
    cudaGetSymbolAddress((void**)&k,     g_k);
    cudaGetSymbolAddress((void**)&v,     g_v);
    cudaGetSymbolAddress((void**)&aop,   g_aop);
    cudaGetSymbolAddress((void**)&wtq,   g_wtq);
    cudaGetSymbolAddress((void**)&wtk,   g_wtk);
    cudaGetSymbolAddress((void**)&wtv,   g_wtv);
    cudaGetSymbolAddress((void**)&wtp,   g_wtp);
    cudaGetSymbolAddress((void**)&wct,   g_wct);
    cudaGetSymbolAddress((void**)&cpart, g_cpart);

    pack_w4_kernel<<<256, 256>>>(Wq, Wk, Wv, Wp, wtq, wtk, wtv, wtp);
    pack_wconv_kernel<<<1024, 256>>>(Wsr, wct);

    conv_part_kernel<<<dim3(MCONV / 32, 4), 256>>>(x, wct, cpart);             // SR conv
    ln_combine_kernel<<<MCONV, 128>>>(cpart, bias, gamma, beta, xrp);          // +bias+LN (permuted out)
    gemm_frag_dual_kernel<<<dim3(MCONV / 64, 2), 256>>>(xrp, wtk, wtv, k, v);  // K,V proj (no smem)
    attn_fused_kernel<<<dim3(NQ / QTILE, HEADS, BATCH), 256>>>(x, wtq, k, v, aop);
    gemm_frag_kernel<<<MQ / 64, 256>>>(aop, wtp, (float*)d_out);               // out proj (no smem)
}